// round 2
// baseline (speedup 1.0000x reference)
#include <cuda_runtime.h>

// ---------------------------------------------------------------------------
// MNIST TWN CNN forward, batch 4096, fp32 — f32x2 packed-FMA version.
//   conv1(1->32,5x5)->BN->ReLU->pool   [stats pass scalar + apply pass f32x2]
//   conv2(32->64,5x5)->BN->ReLU->pool  [f32x2 channel-paired, 13.4 GMAC hot spot]
//   fc1(1024->512)->BN->ReLU           [f32x2 column-paired GEMM]
//   fc2(512->10)+bf2
// All packed ops are bit-exact fp32 (fma.rn.f32x2 == 2x fmaf), accumulation
// order per output unchanged -> identical numerics to R1.
// ---------------------------------------------------------------------------

#define NIMG 4096
typedef unsigned long long u64;

__device__ __forceinline__ u64 pack2(float lo, float hi) {
    u64 r; asm("mov.b64 %0,{%1,%2};" : "=l"(r) : "f"(lo), "f"(hi)); return r;
}
__device__ __forceinline__ u64 rep2(float v) { return pack2(v, v); }
__device__ __forceinline__ void unpack2(u64 p, float& lo, float& hi) {
    asm("mov.b64 {%0,%1},%2;" : "=f"(lo), "=f"(hi) : "l"(p));
}
__device__ __forceinline__ void ffma2(u64& d, u64 a, u64 b) {
    asm("fma.rn.f32x2 %0,%1,%2,%0;" : "+l"(d) : "l"(a), "l"(b));
}
__device__ __forceinline__ u64 add2(u64 a, u64 b) {
    u64 r; asm("add.rn.f32x2 %0,%1,%2;" : "=l"(r) : "l"(a), "l"(b)); return r;
}

// ---- device scratch (static only; no cudaMalloc anywhere) -----------------
static __device__ float g_w1q[32 * 25];
static __device__ u64   g_w2p[32 * 800];        // channel-pair packed (2pc,2pc+1)
static __device__ float g_wf1q[512 * 1024];
static __device__ float g_wf2q[10 * 512];

static __device__ float g_pmax[96][4];

static __device__ double g_sum1[32],  g_sqs1[32];
static __device__ double g_sum2[64],  g_sqs2[64];
static __device__ double g_sum3[512], g_sqs3[512];

static __device__ float g_sc1[32],  g_sh1[32];
static __device__ float g_sc2[64],  g_sh2[64];
static __device__ float g_sc3[512], g_sh3[512];

static __device__ float g_h1[NIMG * 32 * 144];
static __device__ float g_y2[NIMG * 64 * 64];
static __device__ float g_h2[NIMG * 1024];
static __device__ float g_y3[NIMG * 512];

// ---------------------------------------------------------------------------
// abs-max partials (grid MUST be 96). Block 0 also zeros the stats accums.
// ---------------------------------------------------------------------------
__global__ __launch_bounds__(256) void k_absmax(const float* __restrict__ w1, const float* __restrict__ w2,
                                                const float* __restrict__ wf1, const float* __restrict__ wf2) {
    __shared__ float sm[8][4];
    int tid = threadIdx.x;
    if (blockIdx.x == 0) {
        if (tid < 32) { g_sum1[tid] = 0.0; g_sqs1[tid] = 0.0; }
        if (tid < 64) { g_sum2[tid] = 0.0; g_sqs2[tid] = 0.0; }
        g_sum3[tid] = 0.0;       g_sqs3[tid] = 0.0;
        g_sum3[tid + 256] = 0.0; g_sqs3[tid + 256] = 0.0;
    }
    int gid = blockIdx.x * 256 + tid;
    int stride = 96 * 256;
    float m0 = 0.f, m1 = 0.f, m2 = 0.f, m3 = 0.f;
    for (int i = gid; i < 800;    i += stride) m0 = fmaxf(m0, fabsf(w1[i]));
    for (int i = gid; i < 51200;  i += stride) m1 = fmaxf(m1, fabsf(w2[i]));
    for (int i = gid; i < 524288; i += stride) m2 = fmaxf(m2, fabsf(wf1[i]));
    for (int i = gid; i < 5120;   i += stride) m3 = fmaxf(m3, fabsf(wf2[i]));
    #pragma unroll
    for (int off = 16; off; off >>= 1) {
        m0 = fmaxf(m0, __shfl_xor_sync(0xffffffffu, m0, off));
        m1 = fmaxf(m1, __shfl_xor_sync(0xffffffffu, m1, off));
        m2 = fmaxf(m2, __shfl_xor_sync(0xffffffffu, m2, off));
        m3 = fmaxf(m3, __shfl_xor_sync(0xffffffffu, m3, off));
    }
    int w = tid >> 5;
    if ((tid & 31) == 0) { sm[w][0] = m0; sm[w][1] = m1; sm[w][2] = m2; sm[w][3] = m3; }
    __syncthreads();
    if (tid == 0) {
        float r0 = 0.f, r1 = 0.f, r2 = 0.f, r3 = 0.f;
        #pragma unroll
        for (int i = 0; i < 8; i++) {
            r0 = fmaxf(r0, sm[i][0]); r1 = fmaxf(r1, sm[i][1]);
            r2 = fmaxf(r2, sm[i][2]); r3 = fmaxf(r3, sm[i][3]);
        }
        g_pmax[blockIdx.x][0] = r0; g_pmax[blockIdx.x][1] = r1;
        g_pmax[blockIdx.x][2] = r2; g_pmax[blockIdx.x][3] = r3;
    }
}

__device__ __forceinline__ float ternary(float w, float t) {
    return (w > t ? 1.0f : 0.0f) - (w < -t ? 1.0f : 0.0f);
}

__global__ __launch_bounds__(256) void k_quant(const float* __restrict__ w1, const float* __restrict__ w2,
                                               const float* __restrict__ wf1, const float* __restrict__ wf2) {
    float m0 = 0.f, m1 = 0.f, m2 = 0.f, m3 = 0.f;
    for (int i = 0; i < 96; i++) {
        m0 = fmaxf(m0, g_pmax[i][0]); m1 = fmaxf(m1, g_pmax[i][1]);
        m2 = fmaxf(m2, g_pmax[i][2]); m3 = fmaxf(m3, g_pmax[i][3]);
    }
    float t0 = 0.05f * m0, t1 = 0.05f * m1, t2 = 0.05f * m2, t3 = 0.05f * m3;
    int tid = blockIdx.x * blockDim.x + threadIdx.x;
    int stride = gridDim.x * blockDim.x;
    for (int i = tid; i < 800; i += stride) g_w1q[i] = ternary(w1[i], t0);
    for (int i = tid; i < 25600; i += stride) {          // channel-pair packed conv2 weights
        int pc = i / 800, r = i - pc * 800;
        float a = ternary(w2[(2 * pc) * 800 + r], t1);
        float b = ternary(w2[(2 * pc + 1) * 800 + r], t1);
        ((float2*)g_w2p)[i] = make_float2(a, b);
    }
    for (int i = tid; i < 524288; i += stride) g_wf1q[i] = ternary(wf1[i], t2);
    for (int i = tid; i < 5120;   i += stride) g_wf2q[i] = ternary(wf2[i], t3);
}

// ---------------------------------------------------------------------------
// conv1 stats (scalar; ~small). Per-channel sum/sumsq of raw conv output.
// ---------------------------------------------------------------------------
__global__ __launch_bounds__(256) void k_conv1_stats(const float* __restrict__ x) {
    __shared__ float ws[800];
    __shared__ float ssum[32], ssq[32];
    for (int i = threadIdx.x; i < 800; i += 256) ws[i] = g_w1q[i];
    if (threadIdx.x < 32) { ssum[threadIdx.x] = 0.f; ssq[threadIdx.x] = 0.f; }
    __syncthreads();

    float acc[32], acc2[32];
    #pragma unroll
    for (int c = 0; c < 32; c++) { acc[c] = 0.f; acc2[c] = 0.f; }

    int base = blockIdx.x * 2048 + threadIdx.x;
    for (int it = 0; it < 8; it++) {
        int pos = base + it * 256;
        int n  = pos / 576;
        int r  = pos - n * 576;
        int oy = r / 24;
        int ox = r - oy * 24;
        const float* xp = x + n * 784 + oy * 28 + ox;
        float p[25];
        #pragma unroll
        for (int ky = 0; ky < 5; ky++)
            #pragma unroll
            for (int kx = 0; kx < 5; kx++) p[ky * 5 + kx] = xp[ky * 28 + kx];
        #pragma unroll
        for (int c = 0; c < 32; c++) {
            float v = 0.f;
            #pragma unroll
            for (int k = 0; k < 25; k++) v = fmaf(p[k], ws[c * 25 + k], v);
            acc[c] += v;
            acc2[c] = fmaf(v, v, acc2[c]);
        }
    }
    int lane = threadIdx.x & 31;
    #pragma unroll
    for (int c = 0; c < 32; c++) {
        float s = acc[c], q = acc2[c];
        #pragma unroll
        for (int off = 16; off; off >>= 1) {
            s += __shfl_xor_sync(0xffffffffu, s, off);
            q += __shfl_xor_sync(0xffffffffu, q, off);
        }
        if (lane == 0) { atomicAdd(&ssum[c], s); atomicAdd(&ssq[c], q); }
    }
    __syncthreads();
    if (threadIdx.x < 32) {
        atomicAdd(&g_sum1[threadIdx.x], (double)ssum[threadIdx.x]);
        atomicAdd(&g_sqs1[threadIdx.x], (double)ssq[threadIdx.x]);
    }
}

__global__ void k_fin1(const float* __restrict__ g, const float* __restrict__ be) {
    int i = threadIdx.x;
    if (i >= 32) return;
    const double invM = 1.0 / (4096.0 * 576.0);
    double mean = g_sum1[i] * invM;
    double var  = g_sqs1[i] * invM - mean * mean;
    float A = g[i] * rsqrtf((float)var + 1e-5f);
    g_sc1[i] = A;
    g_sh1[i] = be[i] - (float)mean * A;
}

// ---------------------------------------------------------------------------
// conv1 apply: f32x2 over the two pooled-window columns; weights replicated
// (w,w) in SMEM so LDS.64 yields a ready operand.
// ---------------------------------------------------------------------------
__global__ __launch_bounds__(256) void k_conv1_apply(const float* __restrict__ x) {
    __shared__ u64 ws2[800];
    __shared__ float sA[32], sB[32];
    for (int i = threadIdx.x; i < 800; i += 256) ws2[i] = rep2(g_w1q[i]);
    if (threadIdx.x < 32) { sA[threadIdx.x] = g_sc1[threadIdx.x]; sB[threadIdx.x] = g_sh1[threadIdx.x]; }
    __syncthreads();

    int idx = blockIdx.x * 256 + threadIdx.x;      // < 4096*144
    int n = idx / 144;
    int r = idx - n * 144;
    int py = r / 12;
    int px = r - py * 12;
    const float* xp = x + n * 784 + py * 2 * 28 + px * 2;
    float p[36];
    #pragma unroll
    for (int iy = 0; iy < 6; iy++)
        #pragma unroll
        for (int ix = 0; ix < 6; ix++) p[iy * 6 + ix] = xp[iy * 28 + ix];
    // sliding pairs P[r][k] = (p[r][k], p[r][k+1])
    u64 P[30];
    #pragma unroll
    for (int ry = 0; ry < 6; ry++)
        #pragma unroll
        for (int k = 0; k < 5; k++) P[ry * 5 + k] = pack2(p[ry * 6 + k], p[ry * 6 + k + 1]);

    float* hp = g_h1 + n * 4608 + r;
    for (int c = 0; c < 32; c++) {
        u64 v01 = 0ull, v23 = 0ull;                // (v0,v1) top row, (v2,v3) bottom row
        #pragma unroll
        for (int ky = 0; ky < 5; ky++)
            #pragma unroll
            for (int kx = 0; kx < 5; kx++) {
                u64 w = ws2[c * 25 + ky * 5 + kx];
                ffma2(v01, P[ky * 5 + kx], w);
                ffma2(v23, P[(ky + 1) * 5 + kx], w);
            }
        float v0, v1, v2, v3;
        unpack2(v01, v0, v1);
        unpack2(v23, v2, v3);
        float A = sA[c], B = sB[c];
        float m = fmaxf(fmaxf(fmaf(A, v0, B), fmaf(A, v1, B)),
                        fmaxf(fmaf(A, v2, B), fmaf(A, v3, B)));
        hp[c * 144] = fmaxf(m, 0.f);
    }
}

// ---------------------------------------------------------------------------
// conv2: f32x2 channel-paired. 256 thr = 32 channel-pairs x 8 rows.
// Input stored replicated (x,x) in SMEM -> LDS.128 gives 2 ready operands.
// Weights LDG.64 pre-packed per channel pair. 40 FFMA2 per (ci,ky) = 80 MACs.
// ---------------------------------------------------------------------------
__global__ __launch_bounds__(256) void k_conv2() {
    __shared__ u64 sin2[32 * 144];                 // 36 KB
    int tid = threadIdx.x;
    int n = blockIdx.x;
    const float* src = g_h1 + n * 4608;
    for (int i = tid; i < 4608; i += 256) sin2[i] = rep2(src[i]);
    __syncthreads();

    int pc = tid >> 3;                             // channel pair: (2pc, 2pc+1)
    int py = tid & 7;
    const u64* wp = g_w2p + pc * 800;

    u64 acc[8];
    #pragma unroll
    for (int i = 0; i < 8; i++) acc[i] = 0ull;

    for (int ci = 0; ci < 32; ci++) {
        #pragma unroll
        for (int ky = 0; ky < 5; ky++) {
            const ulonglong2* row = (const ulonglong2*)(sin2 + ci * 144 + (py + ky) * 12);
            ulonglong2 u0 = row[0], u1 = row[1], u2 = row[2], u3 = row[3], u4 = row[4], u5 = row[5];
            u64 xr[12] = { u0.x, u0.y, u1.x, u1.y, u2.x, u2.y,
                           u3.x, u3.y, u4.x, u4.y, u5.x, u5.y };
            const u64* wr = wp + ci * 25 + ky * 5;
            u64 w[5] = { wr[0], wr[1], wr[2], wr[3], wr[4] };
            #pragma unroll
            for (int kx = 0; kx < 5; kx++)
                #pragma unroll
                for (int ox = 0; ox < 8; ox++)
                    ffma2(acc[ox], xr[ox + kx], w[kx]);
        }
    }

    float c0r[8], c1r[8];
    u64 sp = 0ull, qp = 0ull;
    #pragma unroll
    for (int ox = 0; ox < 8; ox++) {
        unpack2(acc[ox], c0r[ox], c1r[ox]);
        sp = add2(sp, acc[ox]);
        ffma2(qp, acc[ox], acc[ox]);
    }
    float* d0 = g_y2 + n * 4096 + (2 * pc) * 64 + py * 8;
    ((float4*)d0)[0] = make_float4(c0r[0], c0r[1], c0r[2], c0r[3]);
    ((float4*)d0)[1] = make_float4(c0r[4], c0r[5], c0r[6], c0r[7]);
    float* d1 = d0 + 64;
    ((float4*)d1)[0] = make_float4(c1r[0], c1r[1], c1r[2], c1r[3]);
    ((float4*)d1)[1] = make_float4(c1r[4], c1r[5], c1r[6], c1r[7]);

    #pragma unroll
    for (int off = 1; off < 8; off <<= 1) {        // reduce over the 8 py lanes
        sp = add2(sp, __shfl_xor_sync(0xffffffffu, sp, off));
        qp = add2(qp, __shfl_xor_sync(0xffffffffu, qp, off));
    }
    if (py == 0) {
        float s0, s1, q0, q1;
        unpack2(sp, s0, s1);
        unpack2(qp, q0, q1);
        atomicAdd(&g_sum2[2 * pc],     (double)s0);
        atomicAdd(&g_sum2[2 * pc + 1], (double)s1);
        atomicAdd(&g_sqs2[2 * pc],     (double)q0);
        atomicAdd(&g_sqs2[2 * pc + 1], (double)q1);
    }
}

__global__ void k_fin2(const float* __restrict__ g, const float* __restrict__ be) {
    int i = threadIdx.x;
    if (i >= 64) return;
    const double invM = 1.0 / (4096.0 * 64.0);
    double mean = g_sum2[i] * invM;
    double var  = g_sqs2[i] * invM - mean * mean;
    float A = g[i] * rsqrtf((float)var + 1e-5f);
    g_sc2[i] = A;
    g_sh2[i] = be[i] - (float)mean * A;
}

__global__ __launch_bounds__(256) void k_bnpool2() {
    int idx = blockIdx.x * 256 + threadIdx.x;
    int n = idx >> 10;
    int r = idx & 1023;
    int c = r >> 4;
    int pr = r & 15;
    int py = pr >> 2, px = pr & 3;
    const float* src = g_y2 + n * 4096 + c * 64 + py * 2 * 8 + px * 2;
    float A = g_sc2[c], B = g_sh2[c];
    float m = fmaxf(fmaxf(fmaf(A, src[0], B), fmaf(A, src[1], B)),
                    fmaxf(fmaf(A, src[8], B), fmaf(A, src[9], B)));
    g_h2[idx] = fmaxf(m, 0.f);
}

// ---------------------------------------------------------------------------
// fc1 GEMM: f32x2 column-paired; A tile stored replicated in SMEM.
// ---------------------------------------------------------------------------
__global__ __launch_bounds__(256) void k_fc1() {
    __shared__ u64 As2[16][64];                    // replicated (a,a): 8 KB
    __shared__ float Bs[16][64];
    __shared__ float scol[64], scol2[64];
    int tid = threadIdx.x;
    if (tid < 64) { scol[tid] = 0.f; scol2[tid] = 0.f; }

    int m0 = blockIdx.y * 64;
    int n0 = blockIdx.x * 64;
    int lr = tid >> 2;
    int lk = (tid & 3) * 4;
    const float* Aload = g_h2  + (m0 + lr) * 1024 + lk;
    const float* Bload = g_wf1q + (n0 + lr) * 1024 + lk;
    int tx = tid & 15, ty = tid >> 4;

    u64 accp[4][2];
    #pragma unroll
    for (int i = 0; i < 4; i++) { accp[i][0] = 0ull; accp[i][1] = 0ull; }

    for (int k0 = 0; k0 < 1024; k0 += 16) {
        float4 av = *(const float4*)(Aload + k0);
        float4 bv = *(const float4*)(Bload + k0);
        __syncthreads();
        As2[lk + 0][lr] = rep2(av.x); As2[lk + 1][lr] = rep2(av.y);
        As2[lk + 2][lr] = rep2(av.z); As2[lk + 3][lr] = rep2(av.w);
        Bs[lk + 0][lr] = bv.x; Bs[lk + 1][lr] = bv.y;
        Bs[lk + 2][lr] = bv.z; Bs[lk + 3][lr] = bv.w;
        __syncthreads();
        #pragma unroll
        for (int k = 0; k < 16; k++) {
            const ulonglong2* ap = (const ulonglong2*)&As2[k][ty * 4];
            ulonglong2 aa = ap[0], ab = ap[1];
            float4 b = *(const float4*)&Bs[k][tx * 4];
            u64 b01 = pack2(b.x, b.y), b23 = pack2(b.z, b.w);
            ffma2(accp[0][0], aa.x, b01); ffma2(accp[0][1], aa.x, b23);
            ffma2(accp[1][0], aa.y, b01); ffma2(accp[1][1], aa.y, b23);
            ffma2(accp[2][0], ab.x, b01); ffma2(accp[2][1], ab.x, b23);
            ffma2(accp[3][0], ab.y, b01); ffma2(accp[3][1], ab.y, b23);
        }
    }
    float acc[4][4];
    #pragma unroll
    for (int i = 0; i < 4; i++) {
        unpack2(accp[i][0], acc[i][0], acc[i][1]);
        unpack2(accp[i][1], acc[i][2], acc[i][3]);
    }
    #pragma unroll
    for (int i = 0; i < 4; i++) {
        int row = m0 + ty * 4 + i;
        *(float4*)(g_y3 + row * 512 + n0 + tx * 4) =
            make_float4(acc[i][0], acc[i][1], acc[i][2], acc[i][3]);
    }
    #pragma unroll
    for (int j = 0; j < 4; j++) {
        float s = 0.f, q = 0.f;
        #pragma unroll
        for (int i = 0; i < 4; i++) { s += acc[i][j]; q = fmaf(acc[i][j], acc[i][j], q); }
        atomicAdd(&scol[tx * 4 + j], s);
        atomicAdd(&scol2[tx * 4 + j], q);
    }
    __syncthreads();
    if (tid < 64) {
        atomicAdd(&g_sum3[n0 + tid], (double)scol[tid]);
        atomicAdd(&g_sqs3[n0 + tid], (double)scol2[tid]);
    }
}

__global__ void k_fin3(const float* __restrict__ g, const float* __restrict__ be) {
    int i = threadIdx.x;
    if (i >= 512) return;
    const double invM = 1.0 / 4096.0;
    double mean = g_sum3[i] * invM;
    double var  = g_sqs3[i] * invM - mean * mean;
    float A = g[i] * rsqrtf((float)var + 1e-5f);
    g_sc3[i] = A;
    g_sh3[i] = be[i] - (float)mean * A;
}

__global__ __launch_bounds__(256) void k_fc2(float* __restrict__ out, const float* __restrict__ bf2) {
    __shared__ float sw[5120];
    __shared__ float sA[512], sB[512];
    __shared__ float sb[16];
    for (int i = threadIdx.x; i < 5120; i += 256) sw[i] = g_wf2q[i];
    for (int i = threadIdx.x; i < 512; i += 256) { sA[i] = g_sc3[i]; sB[i] = g_sh3[i]; }
    if (threadIdx.x < 10) sb[threadIdx.x] = bf2[threadIdx.x];
    __syncthreads();

    int warp = threadIdx.x >> 5, lane = threadIdx.x & 31;
    int n = blockIdx.x * 8 + warp;
    const float* yr = g_y3 + n * 512;
    float acc[10];
    #pragma unroll
    for (int o = 0; o < 10; o++) acc[o] = 0.f;
    for (int f = lane; f < 512; f += 32) {
        float a = fmaxf(fmaf(sA[f], yr[f], sB[f]), 0.f);
        #pragma unroll
        for (int o = 0; o < 10; o++) acc[o] = fmaf(a, sw[o * 512 + f], acc[o]);
    }
    #pragma unroll
    for (int o = 0; o < 10; o++) {
        float s = acc[o];
        #pragma unroll
        for (int off = 16; off; off >>= 1) s += __shfl_xor_sync(0xffffffffu, s, off);
        if (lane == 0) out[n * 10 + o] = s + sb[o];
    }
}

// ---------------------------------------------------------------------------
extern "C" void kernel_launch(void* const* d_in, const int* in_sizes, int n_in,
                              void* d_out, int out_size) {
    const float* x   = (const float*)d_in[0];
    const float* w1  = (const float*)d_in[1];
    const float* g1  = (const float*)d_in[3];
    const float* be1 = (const float*)d_in[4];
    const float* w2  = (const float*)d_in[5];
    const float* g2  = (const float*)d_in[7];
    const float* be2 = (const float*)d_in[8];
    const float* wf1 = (const float*)d_in[9];
    const float* g3  = (const float*)d_in[11];
    const float* be3 = (const float*)d_in[12];
    const float* wf2 = (const float*)d_in[13];
    const float* bf2 = (const float*)d_in[14];
    float* out = (float*)d_out;

    k_absmax<<<96, 256>>>(w1, w2, wf1, wf2);       // launch 1 (also zeros stats)
    k_quant<<<512, 256>>>(w1, w2, wf1, wf2);       // launch 2
    k_conv1_stats<<<1152, 256>>>(x);               // launch 3
    k_fin1<<<1, 32>>>(g1, be1);                    // launch 4
    k_conv1_apply<<<2304, 256>>>(x);               // launch 5
    k_conv2<<<4096, 256>>>();                      // launch 6  <- ncu -s 5 target
    k_fin2<<<1, 64>>>(g2, be2);
    k_bnpool2<<<16384, 256>>>();
    dim3 g_fc1(8, 64);
    k_fc1<<<g_fc1, 256>>>();
    k_fin3<<<1, 512>>>(g3, be3);
    k_fc2<<<512, 256>>>(out, bf2);
}

// round 4
// speedup vs baseline: 2.0003x; 2.0003x over previous
#include <cuda_runtime.h>

// ---------------------------------------------------------------------------
// MNIST TWN CNN forward, batch 4096, fp32.
// 7 launches: absmax, conv1(raw+stats+quant), bnpool1, conv2(staged wts),
//             bnpool2, fc1, fc2.  All BN finalizations fused into consumers.
// R4: fix R3 bug (sw1[384..399] uninitialized — tid<400 guard with 384 threads).
// ---------------------------------------------------------------------------

#define NIMG 4096
typedef unsigned long long u64;

__device__ __forceinline__ u64 pack2(float lo, float hi) {
    u64 r; asm("mov.b64 %0,{%1,%2};" : "=l"(r) : "f"(lo), "f"(hi)); return r;
}
__device__ __forceinline__ u64 rep2(float v) { return pack2(v, v); }
__device__ __forceinline__ void unpack2(u64 p, float& lo, float& hi) {
    asm("mov.b64 {%0,%1},%2;" : "=f"(lo), "=f"(hi) : "l"(p));
}
__device__ __forceinline__ void ffma2(u64& d, u64 a, u64 b) {
    asm("fma.rn.f32x2 %0,%1,%2,%0;" : "+l"(d) : "l"(a), "l"(b));
}
__device__ __forceinline__ u64 add2(u64 a, u64 b) {
    u64 r; asm("add.rn.f32x2 %0,%1,%2;" : "=l"(r) : "l"(a), "l"(b)); return r;
}
__device__ __forceinline__ float ternary(float w, float t) {
    return (w > t ? 1.0f : 0.0f) - (w < -t ? 1.0f : 0.0f);
}

// ---- device scratch (static only) -----------------------------------------
static __device__ u64   g_w2p[32 * 800];         // [ci][pc][25] channel-pair packed
static __device__ float g_wf1q[512 * 1024];
static __device__ float g_wf2q[10 * 512];
static __device__ float g_pmax[96][4];

static __device__ double g_sum1[32],  g_sqs1[32];
static __device__ double g_sum2[64],  g_sqs2[64];
static __device__ double g_sum3[512], g_sqs3[512];

static __device__ float g_y1[NIMG * 32 * 576];   // conv1 raw [n][c][24][24] (302 MB)
static __device__ float g_h1[NIMG * 32 * 144];   // pooled    [n][c][12][12] (75.5 MB)
static __device__ float g_y2[NIMG * 64 * 64];    // conv2 raw [n][c][8][8]   (67 MB)
static __device__ float g_h2[NIMG * 1024];       // pooled/flat
static __device__ float g_y3[NIMG * 512];        // fc1 raw

// ---------------------------------------------------------------------------
// Launch 1: abs-max partials (grid MUST be 96). Block 0 zeros stat accums.
// ---------------------------------------------------------------------------
__global__ __launch_bounds__(256) void k_absmax(const float* __restrict__ w1, const float* __restrict__ w2,
                                                const float* __restrict__ wf1, const float* __restrict__ wf2) {
    __shared__ float sm[8][4];
    int tid = threadIdx.x;
    if (blockIdx.x == 0) {
        if (tid < 32) { g_sum1[tid] = 0.0; g_sqs1[tid] = 0.0; }
        if (tid < 64) { g_sum2[tid] = 0.0; g_sqs2[tid] = 0.0; }
        g_sum3[tid] = 0.0;       g_sqs3[tid] = 0.0;
        g_sum3[tid + 256] = 0.0; g_sqs3[tid + 256] = 0.0;
    }
    int gid = blockIdx.x * 256 + tid;
    int stride = 96 * 256;
    float m0 = 0.f, m1 = 0.f, m2 = 0.f, m3 = 0.f;
    for (int i = gid; i < 800;    i += stride) m0 = fmaxf(m0, fabsf(w1[i]));
    for (int i = gid; i < 51200;  i += stride) m1 = fmaxf(m1, fabsf(w2[i]));
    for (int i = gid; i < 524288; i += stride) m2 = fmaxf(m2, fabsf(wf1[i]));
    for (int i = gid; i < 5120;   i += stride) m3 = fmaxf(m3, fabsf(wf2[i]));
    #pragma unroll
    for (int off = 16; off; off >>= 1) {
        m0 = fmaxf(m0, __shfl_xor_sync(0xffffffffu, m0, off));
        m1 = fmaxf(m1, __shfl_xor_sync(0xffffffffu, m1, off));
        m2 = fmaxf(m2, __shfl_xor_sync(0xffffffffu, m2, off));
        m3 = fmaxf(m3, __shfl_xor_sync(0xffffffffu, m3, off));
    }
    int w = tid >> 5;
    if ((tid & 31) == 0) { sm[w][0] = m0; sm[w][1] = m1; sm[w][2] = m2; sm[w][3] = m3; }
    __syncthreads();
    if (tid == 0) {
        float r0 = 0.f, r1 = 0.f, r2 = 0.f, r3 = 0.f;
        #pragma unroll
        for (int i = 0; i < 8; i++) {
            r0 = fmaxf(r0, sm[i][0]); r1 = fmaxf(r1, sm[i][1]);
            r2 = fmaxf(r2, sm[i][2]); r3 = fmaxf(r3, sm[i][3]);
        }
        g_pmax[blockIdx.x][0] = r0; g_pmax[blockIdx.x][1] = r1;
        g_pmax[blockIdx.x][2] = r2; g_pmax[blockIdx.x][3] = r3;
    }
}

// ---------------------------------------------------------------------------
// Launch 2: conv1 raw (y1) + per-channel stats. One block per image.
// 384 threads = 16 channel-pairs x 24 output rows. Channel-pair f32x2.
// Side jobs: quantize w1 into SMEM; quantize w2/wf1/wf2 slices into global.
// ---------------------------------------------------------------------------
__global__ __launch_bounds__(384) void k_conv1(const float* __restrict__ x,  const float* __restrict__ w1,
                                               const float* __restrict__ w2, const float* __restrict__ wf1,
                                               const float* __restrict__ wf2) {
    __shared__ u64 sx[784];          // replicated image
    __shared__ u64 sw1[400];         // [cp][25] packed w1
    __shared__ float sthr[4];
    __shared__ float ssum[32], ssq[32];
    int tid = threadIdx.x, n = blockIdx.x;

    if (tid < 4) {                                    // global thresholds
        float m = 0.f;
        #pragma unroll 8
        for (int i = 0; i < 96; i++) m = fmaxf(m, g_pmax[i][tid]);
        sthr[tid] = 0.05f * m;
    }
    if (tid < 32) { ssum[tid] = 0.f; ssq[tid] = 0.f; }
    __syncthreads();

    for (int i = tid; i < 400; i += 384) {            // pack w1 pairs (FIXED: strided)
        int cp = i / 25, k = i - cp * 25;
        float t0 = sthr[0];
        sw1[i] = pack2(ternary(w1[(2 * cp) * 25 + k], t0),
                       ternary(w1[(2 * cp + 1) * 25 + k], t0));
    }
    for (int i = tid; i < 784; i += 384) sx[i] = rep2(x[n * 784 + i]);

    // distributed global quantization (each unit exactly once across the grid)
    {
        int gu = n * 384 + tid;
        if (gu < 25600) {                             // g_w2p [ci][pc][25]
            int ci = gu / 800, r = gu - ci * 800;
            int pc = r / 25, k = r - pc * 25;
            float t1 = sthr[1];
            ((float2*)g_w2p)[gu] = make_float2(ternary(w2[(2 * pc) * 800 + ci * 25 + k], t1),
                                               ternary(w2[(2 * pc + 1) * 800 + ci * 25 + k], t1));
        } else if (gu < 25600 + 524288) {
            g_wf1q[gu - 25600] = ternary(wf1[gu - 25600], sthr[2]);
        } else if (gu < 25600 + 524288 + 5120) {
            g_wf2q[gu - 549888] = ternary(wf2[gu - 549888], sthr[3]);
        }
    }
    __syncthreads();

    int cp = tid / 24, oy = tid - cp * 24;
    const u64* wbase = sw1 + cp * 25;
    u64 sp = 0ull, qp = 0ull;
    float* yb0 = g_y1 + n * 18432 + (2 * cp) * 576 + oy * 24;
    float* yb1 = yb0 + 576;

    #pragma unroll
    for (int ob = 0; ob < 24; ob += 6) {
        u64 acc[6] = {0ull, 0ull, 0ull, 0ull, 0ull, 0ull};
        #pragma unroll
        for (int ky = 0; ky < 5; ky++) {
            const ulonglong2* xr = (const ulonglong2*)(sx + (oy + ky) * 28 + ob);
            ulonglong2 v0 = xr[0], v1 = xr[1], v2 = xr[2], v3 = xr[3], v4 = xr[4];
            u64 xv[10] = { v0.x, v0.y, v1.x, v1.y, v2.x, v2.y, v3.x, v3.y, v4.x, v4.y };
            const u64* wr = wbase + ky * 5;
            u64 w0 = wr[0], w1v = wr[1], w2v = wr[2], w3v = wr[3], w4v = wr[4];
            #pragma unroll
            for (int o = 0; o < 6; o++) {
                ffma2(acc[o], xv[o],     w0);
                ffma2(acc[o], xv[o + 1], w1v);
                ffma2(acc[o], xv[o + 2], w2v);
                ffma2(acc[o], xv[o + 3], w3v);
                ffma2(acc[o], xv[o + 4], w4v);
            }
        }
        float c0[6], c1[6];
        #pragma unroll
        for (int o = 0; o < 6; o++) {
            unpack2(acc[o], c0[o], c1[o]);
            sp = add2(sp, acc[o]);
            ffma2(qp, acc[o], acc[o]);
        }
        ((float2*)(yb0 + ob))[0] = make_float2(c0[0], c0[1]);
        ((float2*)(yb0 + ob))[1] = make_float2(c0[2], c0[3]);
        ((float2*)(yb0 + ob))[2] = make_float2(c0[4], c0[5]);
        ((float2*)(yb1 + ob))[0] = make_float2(c1[0], c1[1]);
        ((float2*)(yb1 + ob))[1] = make_float2(c1[2], c1[3]);
        ((float2*)(yb1 + ob))[2] = make_float2(c1[4], c1[5]);
    }
    float s0, s1, q0, q1;
    unpack2(sp, s0, s1);
    unpack2(qp, q0, q1);
    atomicAdd(&ssum[2 * cp],     s0);
    atomicAdd(&ssum[2 * cp + 1], s1);
    atomicAdd(&ssq[2 * cp],      q0);
    atomicAdd(&ssq[2 * cp + 1],  q1);
    __syncthreads();
    if (tid < 32) {
        atomicAdd(&g_sum1[tid], (double)ssum[tid]);
        atomicAdd(&g_sqs1[tid], (double)ssq[tid]);
    }
}

// ---------------------------------------------------------------------------
// Launch 3: BN(fin1 inline) + ReLU + maxpool y1 -> h1. Pure streaming.
// ---------------------------------------------------------------------------
__global__ __launch_bounds__(256) void k_bnpool1(const float* __restrict__ g, const float* __restrict__ be) {
    __shared__ float sA[32], sB[32];
    if (threadIdx.x < 32) {
        int c = threadIdx.x;
        const double invM = 1.0 / (4096.0 * 576.0);
        double mean = g_sum1[c] * invM;
        double var  = g_sqs1[c] * invM - mean * mean;
        float A = g[c] * rsqrtf((float)var + 1e-5f);
        sA[c] = A;
        sB[c] = be[c] - (float)mean * A;
    }
    __syncthreads();
    int idx = blockIdx.x * 256 + threadIdx.x;          // < 4096*32*144
    int n = idx / 4608;
    int r = idx - n * 4608;
    int c = r / 144;
    int p = r - c * 144;
    int py = p / 12, px = p - py * 12;
    const float* src = g_y1 + n * 18432 + c * 576 + py * 48 + px * 2;
    float2 a = *(const float2*)src;
    float2 b = *(const float2*)(src + 24);
    float A = sA[c], B = sB[c];
    float m = fmaxf(fmaxf(fmaf(A, a.x, B), fmaf(A, a.y, B)),
                    fmaxf(fmaf(A, b.x, B), fmaf(A, b.y, B)));
    g_h1[idx] = fmaxf(m, 0.f);
}

// ---------------------------------------------------------------------------
// Launch 4 (PROFILED): conv2, f32x2 channel-paired, SMEM-staged weights
// (double-buffered, prefetch ci+1 during compute of ci). One block per image.
// ---------------------------------------------------------------------------
__global__ __launch_bounds__(256) void k_conv2() {
    __shared__ u64 sin2[4608];                 // 36 KB replicated input
    __shared__ u64 swt[2][800];                // 12.5 KB weight double buffer
    int tid = threadIdx.x;
    int n = blockIdx.x;
    const float* src = g_h1 + n * 4608;
    for (int i = tid; i < 4608; i += 256) sin2[i] = rep2(src[i]);
    for (int j = tid; j < 800; j += 256) swt[0][j] = g_w2p[j];
    __syncthreads();

    int pc = tid >> 3;
    int py = tid & 7;

    u64 acc[8];
    #pragma unroll
    for (int i = 0; i < 8; i++) acc[i] = 0ull;

    for (int ci = 0; ci < 32; ci++) {
        if (ci < 31) {
            const u64* wsrc = g_w2p + (ci + 1) * 800;
            for (int j = tid; j < 800; j += 256) swt[(ci + 1) & 1][j] = wsrc[j];
        }
        const u64* wp = swt[ci & 1] + pc * 25;
        #pragma unroll
        for (int ky = 0; ky < 5; ky++) {
            const ulonglong2* row = (const ulonglong2*)(sin2 + ci * 144 + (py + ky) * 12);
            ulonglong2 u0 = row[0], u1 = row[1], u2 = row[2], u3 = row[3], u4 = row[4], u5 = row[5];
            u64 xr[12] = { u0.x, u0.y, u1.x, u1.y, u2.x, u2.y,
                           u3.x, u3.y, u4.x, u4.y, u5.x, u5.y };
            const u64* wr = wp + ky * 5;
            u64 w0 = wr[0], w1v = wr[1], w2v = wr[2], w3v = wr[3], w4v = wr[4];
            #pragma unroll
            for (int ox = 0; ox < 8; ox++) {
                ffma2(acc[ox], xr[ox],     w0);
                ffma2(acc[ox], xr[ox + 1], w1v);
                ffma2(acc[ox], xr[ox + 2], w2v);
                ffma2(acc[ox], xr[ox + 3], w3v);
                ffma2(acc[ox], xr[ox + 4], w4v);
            }
        }
        __syncthreads();
    }

    float c0r[8], c1r[8];
    u64 sp = 0ull, qp = 0ull;
    #pragma unroll
    for (int ox = 0; ox < 8; ox++) {
        unpack2(acc[ox], c0r[ox], c1r[ox]);
        sp = add2(sp, acc[ox]);
        ffma2(qp, acc[ox], acc[ox]);
    }
    float* d0 = g_y2 + n * 4096 + (2 * pc) * 64 + py * 8;
    ((float4*)d0)[0] = make_float4(c0r[0], c0r[1], c0r[2], c0r[3]);
    ((float4*)d0)[1] = make_float4(c0r[4], c0r[5], c0r[6], c0r[7]);
    float* d1 = d0 + 64;
    ((float4*)d1)[0] = make_float4(c1r[0], c1r[1], c1r[2], c1r[3]);
    ((float4*)d1)[1] = make_float4(c1r[4], c1r[5], c1r[6], c1r[7]);

    #pragma unroll
    for (int off = 1; off < 8; off <<= 1) {
        sp = add2(sp, __shfl_xor_sync(0xffffffffu, sp, off));
        qp = add2(qp, __shfl_xor_sync(0xffffffffu, qp, off));
    }
    if (py == 0) {
        float s0, s1, q0, q1;
        unpack2(sp, s0, s1);
        unpack2(qp, q0, q1);
        atomicAdd(&g_sum2[2 * pc],     (double)s0);
        atomicAdd(&g_sum2[2 * pc + 1], (double)s1);
        atomicAdd(&g_sqs2[2 * pc],     (double)q0);
        atomicAdd(&g_sqs2[2 * pc + 1], (double)q1);
    }
}

// ---------------------------------------------------------------------------
// Launch 5: BN(fin2 inline) + ReLU + maxpool y2 -> h2. 4 outputs/thread.
// ---------------------------------------------------------------------------
__global__ __launch_bounds__(256) void k_bnpool2(const float* __restrict__ g, const float* __restrict__ be) {
    __shared__ float sA[64], sB[64];
    if (threadIdx.x < 64) {
        int c = threadIdx.x;
        const double invM = 1.0 / (4096.0 * 64.0);
        double mean = g_sum2[c] * invM;
        double var  = g_sqs2[c] * invM - mean * mean;
        float A = g[c] * rsqrtf((float)var + 1e-5f);
        sA[c] = A;
        sB[c] = be[c] - (float)mean * A;
    }
    __syncthreads();
    int t = blockIdx.x * 256 + threadIdx.x;            // < 1048576
    int base = t * 4;
    int n = base >> 10;
    int r = base & 1023;
    int c = r >> 4;
    int py = (r & 15) >> 2;
    const float* src = g_y2 + n * 4096 + c * 64 + py * 16;
    float4 a = ((const float4*)src)[0];
    float4 b = ((const float4*)src)[1];
    float4 e = ((const float4*)src)[2];
    float4 d = ((const float4*)src)[3];
    float A = sA[c], B = sB[c];
    float4 o;
    o.x = fmaxf(fmaxf(fmaxf(fmaf(A, a.x, B), fmaf(A, a.y, B)), fmaxf(fmaf(A, e.x, B), fmaf(A, e.y, B))), 0.f);
    o.y = fmaxf(fmaxf(fmaxf(fmaf(A, a.z, B), fmaf(A, a.w, B)), fmaxf(fmaf(A, e.z, B), fmaf(A, e.w, B))), 0.f);
    o.z = fmaxf(fmaxf(fmaxf(fmaf(A, b.x, B), fmaf(A, b.y, B)), fmaxf(fmaf(A, d.x, B), fmaf(A, d.y, B))), 0.f);
    o.w = fmaxf(fmaxf(fmaxf(fmaf(A, b.z, B), fmaf(A, b.w, B)), fmaxf(fmaf(A, d.z, B), fmaf(A, d.w, B))), 0.f);
    *(float4*)(g_h2 + base) = o;
}

// ---------------------------------------------------------------------------
// Launch 6: fc1 GEMM (f32x2 column-paired) + column stats.
// ---------------------------------------------------------------------------
__global__ __launch_bounds__(256) void k_fc1() {
    __shared__ u64 As2[16][64];
    __shared__ float Bs[16][64];
    __shared__ float scol[64], scol2[64];
    int tid = threadIdx.x;
    if (tid < 64) { scol[tid] = 0.f; scol2[tid] = 0.f; }

    int m0 = blockIdx.y * 64;
    int n0 = blockIdx.x * 64;
    int lr = tid >> 2;
    int lk = (tid & 3) * 4;
    const float* Aload = g_h2   + (m0 + lr) * 1024 + lk;
    const float* Bload = g_wf1q + (n0 + lr) * 1024 + lk;
    int tx = tid & 15, ty = tid >> 4;

    u64 accp[4][2];
    #pragma unroll
    for (int i = 0; i < 4; i++) { accp[i][0] = 0ull; accp[i][1] = 0ull; }

    for (int k0 = 0; k0 < 1024; k0 += 16) {
        float4 av = *(const float4*)(Aload + k0);
        float4 bv = *(const float4*)(Bload + k0);
        __syncthreads();
        As2[lk + 0][lr] = rep2(av.x); As2[lk + 1][lr] = rep2(av.y);
        As2[lk + 2][lr] = rep2(av.z); As2[lk + 3][lr] = rep2(av.w);
        Bs[lk + 0][lr] = bv.x; Bs[lk + 1][lr] = bv.y;
        Bs[lk + 2][lr] = bv.z; Bs[lk + 3][lr] = bv.w;
        __syncthreads();
        #pragma unroll
        for (int k = 0; k < 16; k++) {
            const ulonglong2* ap = (const ulonglong2*)&As2[k][ty * 4];
            ulonglong2 aa = ap[0], ab = ap[1];
            float4 b = *(const float4*)&Bs[k][tx * 4];
            u64 b01 = pack2(b.x, b.y), b23 = pack2(b.z, b.w);
            ffma2(accp[0][0], aa.x, b01); ffma2(accp[0][1], aa.x, b23);
            ffma2(accp[1][0], aa.y, b01); ffma2(accp[1][1], aa.y, b23);
            ffma2(accp[2][0], ab.x, b01); ffma2(accp[2][1], ab.x, b23);
            ffma2(accp[3][0], ab.y, b01); ffma2(accp[3][1], ab.y, b23);
        }
    }
    float acc[4][4];
    #pragma unroll
    for (int i = 0; i < 4; i++) {
        unpack2(accp[i][0], acc[i][0], acc[i][1]);
        unpack2(accp[i][1], acc[i][2], acc[i][3]);
    }
    #pragma unroll
    for (int i = 0; i < 4; i++) {
        int row = m0 + ty * 4 + i;
        *(float4*)(g_y3 + row * 512 + n0 + tx * 4) =
            make_float4(acc[i][0], acc[i][1], acc[i][2], acc[i][3]);
    }
    #pragma unroll
    for (int j = 0; j < 4; j++) {
        float s = 0.f, q = 0.f;
        #pragma unroll
        for (int i = 0; i < 4; i++) { s += acc[i][j]; q = fmaf(acc[i][j], acc[i][j], q); }
        atomicAdd(&scol[tx * 4 + j], s);
        atomicAdd(&scol2[tx * 4 + j], q);
    }
    __syncthreads();
    if (tid < 64) {
        atomicAdd(&g_sum3[n0 + tid], (double)scol[tid]);
        atomicAdd(&g_sqs3[n0 + tid], (double)scol2[tid]);
    }
}

// ---------------------------------------------------------------------------
// Launch 7: fc2 fused with bn1d(fin3 inline)+relu. Warp per row.
// ---------------------------------------------------------------------------
__global__ __launch_bounds__(256) void k_fc2(float* __restrict__ out, const float* __restrict__ bf2,
                                             const float* __restrict__ g3, const float* __restrict__ be3) {
    __shared__ float sw[5120];
    __shared__ float sA[512], sB[512];
    __shared__ float sb[16];
    for (int i = threadIdx.x; i < 5120; i += 256) sw[i] = g_wf2q[i];
    for (int i = threadIdx.x; i < 512; i += 256) {
        const double invM = 1.0 / 4096.0;
        double mean = g_sum3[i] * invM;
        double var  = g_sqs3[i] * invM - mean * mean;
        float A = g3[i] * rsqrtf((float)var + 1e-5f);
        sA[i] = A;
        sB[i] = be3[i] - (float)mean * A;
    }
    if (threadIdx.x < 10) sb[threadIdx.x] = bf2[threadIdx.x];
    __syncthreads();

    int warp = threadIdx.x >> 5, lane = threadIdx.x & 31;
    int n = blockIdx.x * 8 + warp;
    const float* yr = g_y3 + n * 512;
    float acc[10];
    #pragma unroll
    for (int o = 0; o < 10; o++) acc[o] = 0.f;
    for (int f = lane; f < 512; f += 32) {
        float a = fmaxf(fmaf(sA[f], yr[f], sB[f]), 0.f);
        #pragma unroll
        for (int o = 0; o < 10; o++) acc[o] = fmaf(a, sw[o * 512 + f], acc[o]);
    }
    #pragma unroll
    for (int o = 0; o < 10; o++) {
        float s = acc[o];
        #pragma unroll
        for (int off = 16; off; off >>= 1) s += __shfl_xor_sync(0xffffffffu, s, off);
        if (lane == 0) out[n * 10 + o] = s + sb[o];
    }
}

// ---------------------------------------------------------------------------
extern "C" void kernel_launch(void* const* d_in, const int* in_sizes, int n_in,
                              void* d_out, int out_size) {
    const float* x   = (const float*)d_in[0];
    const float* w1  = (const float*)d_in[1];
    const float* g1  = (const float*)d_in[3];
    const float* be1 = (const float*)d_in[4];
    const float* w2  = (const float*)d_in[5];
    const float* g2  = (const float*)d_in[7];
    const float* be2 = (const float*)d_in[8];
    const float* wf1 = (const float*)d_in[9];
    const float* g3  = (const float*)d_in[11];
    const float* be3 = (const float*)d_in[12];
    const float* wf2 = (const float*)d_in[13];
    const float* bf2 = (const float*)d_in[14];
    float* out = (float*)d_out;

    k_absmax<<<96, 256>>>(w1, w2, wf1, wf2);        // 1
    k_conv1<<<4096, 384>>>(x, w1, w2, wf1, wf2);    // 2
    k_bnpool1<<<73728, 256>>>(g1, be1);             // 3
    k_conv2<<<4096, 256>>>();                       // 4  <- profiled
    k_bnpool2<<<4096, 256>>>(g2, be2);              // 5
    dim3 g_fc1(8, 64);
    k_fc1<<<g_fc1, 256>>>();                        // 6
    k_fc2<<<512, 256>>>(out, bf2, g3, be3);         // 7
}

// round 5
// speedup vs baseline: 2.9224x; 1.4610x over previous
#include <cuda_runtime.h>

// ---------------------------------------------------------------------------
// MNIST TWN CNN forward, batch 4096, fp32.
// 7 launches: absmax, conv1(raw+stats+quant), bnpool1, conv2, bnpool2, fc1, fc2.
// R5: conv2 L1-traffic cut (scalar smem input + row-paired threads); fc1 scalar A.
// ---------------------------------------------------------------------------

#define NIMG 4096
typedef unsigned long long u64;

__device__ __forceinline__ u64 pack2(float lo, float hi) {
    u64 r; asm("mov.b64 %0,{%1,%2};" : "=l"(r) : "f"(lo), "f"(hi)); return r;
}
__device__ __forceinline__ u64 rep2(float v) { return pack2(v, v); }
__device__ __forceinline__ void unpack2(u64 p, float& lo, float& hi) {
    asm("mov.b64 {%0,%1},%2;" : "=f"(lo), "=f"(hi) : "l"(p));
}
__device__ __forceinline__ void ffma2(u64& d, u64 a, u64 b) {
    asm("fma.rn.f32x2 %0,%1,%2,%0;" : "+l"(d) : "l"(a), "l"(b));
}
__device__ __forceinline__ u64 add2(u64 a, u64 b) {
    u64 r; asm("add.rn.f32x2 %0,%1,%2;" : "=l"(r) : "l"(a), "l"(b)); return r;
}
__device__ __forceinline__ float ternary(float w, float t) {
    return (w > t ? 1.0f : 0.0f) - (w < -t ? 1.0f : 0.0f);
}

// ---- device scratch (static only) -----------------------------------------
static __device__ u64   g_w2p[32 * 800];         // [ci][pc][25] channel-pair packed
static __device__ float g_wf1q[512 * 1024];
static __device__ float g_wf2q[10 * 512];
static __device__ float g_pmax[96][4];

static __device__ double g_sum1[32],  g_sqs1[32];
static __device__ double g_sum2[64],  g_sqs2[64];
static __device__ double g_sum3[512], g_sqs3[512];

static __device__ float g_y1[NIMG * 32 * 576];   // conv1 raw [n][c][24][24]
static __device__ float g_h1[NIMG * 32 * 144];   // pooled    [n][c][12][12]
static __device__ float g_y2[NIMG * 64 * 64];    // conv2 raw [n][c][8][8]
static __device__ float g_h2[NIMG * 1024];       // pooled/flat
static __device__ float g_y3[NIMG * 512];        // fc1 raw

// ---------------------------------------------------------------------------
// Launch 1: abs-max partials (grid MUST be 96). Block 0 zeros stat accums.
// ---------------------------------------------------------------------------
__global__ __launch_bounds__(256) void k_absmax(const float* __restrict__ w1, const float* __restrict__ w2,
                                                const float* __restrict__ wf1, const float* __restrict__ wf2) {
    __shared__ float sm[8][4];
    int tid = threadIdx.x;
    if (blockIdx.x == 0) {
        if (tid < 32) { g_sum1[tid] = 0.0; g_sqs1[tid] = 0.0; }
        if (tid < 64) { g_sum2[tid] = 0.0; g_sqs2[tid] = 0.0; }
        g_sum3[tid] = 0.0;       g_sqs3[tid] = 0.0;
        g_sum3[tid + 256] = 0.0; g_sqs3[tid + 256] = 0.0;
    }
    int gid = blockIdx.x * 256 + tid;
    int stride = 96 * 256;
    float m0 = 0.f, m1 = 0.f, m2 = 0.f, m3 = 0.f;
    for (int i = gid; i < 800;    i += stride) m0 = fmaxf(m0, fabsf(w1[i]));
    for (int i = gid; i < 51200;  i += stride) m1 = fmaxf(m1, fabsf(w2[i]));
    for (int i = gid; i < 524288; i += stride) m2 = fmaxf(m2, fabsf(wf1[i]));
    for (int i = gid; i < 5120;   i += stride) m3 = fmaxf(m3, fabsf(wf2[i]));
    #pragma unroll
    for (int off = 16; off; off >>= 1) {
        m0 = fmaxf(m0, __shfl_xor_sync(0xffffffffu, m0, off));
        m1 = fmaxf(m1, __shfl_xor_sync(0xffffffffu, m1, off));
        m2 = fmaxf(m2, __shfl_xor_sync(0xffffffffu, m2, off));
        m3 = fmaxf(m3, __shfl_xor_sync(0xffffffffu, m3, off));
    }
    int w = tid >> 5;
    if ((tid & 31) == 0) { sm[w][0] = m0; sm[w][1] = m1; sm[w][2] = m2; sm[w][3] = m3; }
    __syncthreads();
    if (tid == 0) {
        float r0 = 0.f, r1 = 0.f, r2 = 0.f, r3 = 0.f;
        #pragma unroll
        for (int i = 0; i < 8; i++) {
            r0 = fmaxf(r0, sm[i][0]); r1 = fmaxf(r1, sm[i][1]);
            r2 = fmaxf(r2, sm[i][2]); r3 = fmaxf(r3, sm[i][3]);
        }
        g_pmax[blockIdx.x][0] = r0; g_pmax[blockIdx.x][1] = r1;
        g_pmax[blockIdx.x][2] = r2; g_pmax[blockIdx.x][3] = r3;
    }
}

// ---------------------------------------------------------------------------
// Launch 2: conv1 raw (y1) + per-channel stats. One block per image.
// ---------------------------------------------------------------------------
__global__ __launch_bounds__(384) void k_conv1(const float* __restrict__ x,  const float* __restrict__ w1,
                                               const float* __restrict__ w2, const float* __restrict__ wf1,
                                               const float* __restrict__ wf2) {
    __shared__ u64 sx[784];
    __shared__ u64 sw1[400];
    __shared__ float sthr[4];
    __shared__ float ssum[32], ssq[32];
    int tid = threadIdx.x, n = blockIdx.x;

    if (tid < 4) {
        float m = 0.f;
        #pragma unroll 8
        for (int i = 0; i < 96; i++) m = fmaxf(m, g_pmax[i][tid]);
        sthr[tid] = 0.05f * m;
    }
    if (tid < 32) { ssum[tid] = 0.f; ssq[tid] = 0.f; }
    __syncthreads();

    for (int i = tid; i < 400; i += 384) {
        int cp = i / 25, k = i - cp * 25;
        float t0 = sthr[0];
        sw1[i] = pack2(ternary(w1[(2 * cp) * 25 + k], t0),
                       ternary(w1[(2 * cp + 1) * 25 + k], t0));
    }
    for (int i = tid; i < 784; i += 384) sx[i] = rep2(x[n * 784 + i]);

    {
        int gu = n * 384 + tid;
        if (gu < 25600) {
            int ci = gu / 800, r = gu - ci * 800;
            int pc = r / 25, k = r - pc * 25;
            float t1 = sthr[1];
            ((float2*)g_w2p)[gu] = make_float2(ternary(w2[(2 * pc) * 800 + ci * 25 + k], t1),
                                               ternary(w2[(2 * pc + 1) * 800 + ci * 25 + k], t1));
        } else if (gu < 25600 + 524288) {
            g_wf1q[gu - 25600] = ternary(wf1[gu - 25600], sthr[2]);
        } else if (gu < 25600 + 524288 + 5120) {
            g_wf2q[gu - 549888] = ternary(wf2[gu - 549888], sthr[3]);
        }
    }
    __syncthreads();

    int cp = tid / 24, oy = tid - cp * 24;
    const u64* wbase = sw1 + cp * 25;
    u64 sp = 0ull, qp = 0ull;
    float* yb0 = g_y1 + n * 18432 + (2 * cp) * 576 + oy * 24;
    float* yb1 = yb0 + 576;

    #pragma unroll
    for (int ob = 0; ob < 24; ob += 6) {
        u64 acc[6] = {0ull, 0ull, 0ull, 0ull, 0ull, 0ull};
        #pragma unroll
        for (int ky = 0; ky < 5; ky++) {
            const ulonglong2* xr = (const ulonglong2*)(sx + (oy + ky) * 28 + ob);
            ulonglong2 v0 = xr[0], v1 = xr[1], v2 = xr[2], v3 = xr[3], v4 = xr[4];
            u64 xv[10] = { v0.x, v0.y, v1.x, v1.y, v2.x, v2.y, v3.x, v3.y, v4.x, v4.y };
            const u64* wr = wbase + ky * 5;
            u64 w0 = wr[0], w1v = wr[1], w2v = wr[2], w3v = wr[3], w4v = wr[4];
            #pragma unroll
            for (int o = 0; o < 6; o++) {
                ffma2(acc[o], xv[o],     w0);
                ffma2(acc[o], xv[o + 1], w1v);
                ffma2(acc[o], xv[o + 2], w2v);
                ffma2(acc[o], xv[o + 3], w3v);
                ffma2(acc[o], xv[o + 4], w4v);
            }
        }
        float c0[6], c1[6];
        #pragma unroll
        for (int o = 0; o < 6; o++) {
            unpack2(acc[o], c0[o], c1[o]);
            sp = add2(sp, acc[o]);
            ffma2(qp, acc[o], acc[o]);
        }
        ((float2*)(yb0 + ob))[0] = make_float2(c0[0], c0[1]);
        ((float2*)(yb0 + ob))[1] = make_float2(c0[2], c0[3]);
        ((float2*)(yb0 + ob))[2] = make_float2(c0[4], c0[5]);
        ((float2*)(yb1 + ob))[0] = make_float2(c1[0], c1[1]);
        ((float2*)(yb1 + ob))[1] = make_float2(c1[2], c1[3]);
        ((float2*)(yb1 + ob))[2] = make_float2(c1[4], c1[5]);
    }
    float s0, s1, q0, q1;
    unpack2(sp, s0, s1);
    unpack2(qp, q0, q1);
    atomicAdd(&ssum[2 * cp],     s0);
    atomicAdd(&ssum[2 * cp + 1], s1);
    atomicAdd(&ssq[2 * cp],      q0);
    atomicAdd(&ssq[2 * cp + 1],  q1);
    __syncthreads();
    if (tid < 32) {
        atomicAdd(&g_sum1[tid], (double)ssum[tid]);
        atomicAdd(&g_sqs1[tid], (double)ssq[tid]);
    }
}

// ---------------------------------------------------------------------------
// Launch 3: BN + ReLU + maxpool y1 -> h1.
// ---------------------------------------------------------------------------
__global__ __launch_bounds__(256) void k_bnpool1(const float* __restrict__ g, const float* __restrict__ be) {
    __shared__ float sA[32], sB[32];
    if (threadIdx.x < 32) {
        int c = threadIdx.x;
        const double invM = 1.0 / (4096.0 * 576.0);
        double mean = g_sum1[c] * invM;
        double var  = g_sqs1[c] * invM - mean * mean;
        float A = g[c] * rsqrtf((float)var + 1e-5f);
        sA[c] = A;
        sB[c] = be[c] - (float)mean * A;
    }
    __syncthreads();
    int idx = blockIdx.x * 256 + threadIdx.x;
    int n = idx / 4608;
    int r = idx - n * 4608;
    int c = r / 144;
    int p = r - c * 144;
    int py = p / 12, px = p - py * 12;
    const float* src = g_y1 + n * 18432 + c * 576 + py * 48 + px * 2;
    float2 a = *(const float2*)src;
    float2 b = *(const float2*)(src + 24);
    float A = sA[c], B = sB[c];
    float m = fmaxf(fmaxf(fmaf(A, a.x, B), fmaf(A, a.y, B)),
                    fmaxf(fmaf(A, b.x, B), fmaf(A, b.y, B)));
    g_h1[idx] = fmaxf(m, 0.f);
}

// ---------------------------------------------------------------------------
// Launch 4 (PROFILED): conv2.  2 images/CTA, 256 thr = 2img x 32pc x 4 rowpairs.
// Scalar (non-replicated) input in SMEM; rep2 in registers. Each thread does
// output rows 2q,2q+1 sharing 6 input rows via sliding weight-row window.
// Weights double-buffered per ci. Lane traffic: 488B per 800 MACs per ci.
// ---------------------------------------------------------------------------
__global__ __launch_bounds__(256) void k_conv2() {
    __shared__ float sin_[2][4608];            // 36.9 KB scalar input
    __shared__ u64 swt[2][800];                // 12.8 KB weight double buffer
    int tid = threadIdx.x;
    int n0 = blockIdx.x * 2;

    const float4* src = (const float4*)(g_h1 + n0 * 4608);
    float4* dst4 = (float4*)sin_;
    for (int i = tid; i < 2304; i += 256) dst4[i] = src[i];
    for (int j = tid; j < 800; j += 256) swt[0][j] = g_w2p[j];
    __syncthreads();

    int img = tid >> 7;
    int t   = tid & 127;
    int pc  = t >> 2;                          // channel pair (2pc, 2pc+1)
    int q   = t & 3;                           // output rows 2q, 2q+1
    const float* ib = sin_[img] + q * 24;      // + ci*144 + rr*12

    u64 acc[2][8];
    #pragma unroll
    for (int oy = 0; oy < 2; oy++)
        #pragma unroll
        for (int px = 0; px < 8; px++) acc[oy][px] = 0ull;

    for (int ci = 0; ci < 32; ci++) {
        if (ci < 31) {
            const u64* ws = g_w2p + (ci + 1) * 800;
            for (int j = tid; j < 800; j += 256) swt[(ci + 1) & 1][j] = ws[j];
        }
        const u64* wp = swt[ci & 1] + pc * 25;
        const float* rb = ib + ci * 144;
        u64 pw0, pw1, pw2, pw3, pw4;
        pw0 = pw1 = pw2 = pw3 = pw4 = 0ull;
        #pragma unroll
        for (int rr = 0; rr < 6; rr++) {
            float4 f0 = *(const float4*)(rb + rr * 12);
            float4 f1 = *(const float4*)(rb + rr * 12 + 4);
            float4 f2 = *(const float4*)(rb + rr * 12 + 8);
            u64 R[12] = { rep2(f0.x), rep2(f0.y), rep2(f0.z), rep2(f0.w),
                          rep2(f1.x), rep2(f1.y), rep2(f1.z), rep2(f1.w),
                          rep2(f2.x), rep2(f2.y), rep2(f2.z), rep2(f2.w) };
            if (rr >= 1) {                     // oy=1, ky = rr-1, uses prev weight row
                #pragma unroll
                for (int px = 0; px < 8; px++) {
                    ffma2(acc[1][px], R[px],     pw0);
                    ffma2(acc[1][px], R[px + 1], pw1);
                    ffma2(acc[1][px], R[px + 2], pw2);
                    ffma2(acc[1][px], R[px + 3], pw3);
                    ffma2(acc[1][px], R[px + 4], pw4);
                }
            }
            if (rr < 5) {                      // oy=0, ky = rr
                const u64* wr = wp + rr * 5;
                u64 c0 = wr[0], c1 = wr[1], c2 = wr[2], c3 = wr[3], c4 = wr[4];
                #pragma unroll
                for (int px = 0; px < 8; px++) {
                    ffma2(acc[0][px], R[px],     c0);
                    ffma2(acc[0][px], R[px + 1], c1);
                    ffma2(acc[0][px], R[px + 2], c2);
                    ffma2(acc[0][px], R[px + 3], c3);
                    ffma2(acc[0][px], R[px + 4], c4);
                }
                pw0 = c0; pw1 = c1; pw2 = c2; pw3 = c3; pw4 = c4;
            }
        }
        __syncthreads();
    }

    int n = n0 + img;
    u64 sp = 0ull, qp = 0ull;
    #pragma unroll
    for (int oy = 0; oy < 2; oy++) {
        float c0r[8], c1r[8];
        #pragma unroll
        for (int px = 0; px < 8; px++) {
            unpack2(acc[oy][px], c0r[px], c1r[px]);
            sp = add2(sp, acc[oy][px]);
            ffma2(qp, acc[oy][px], acc[oy][px]);
        }
        float* d0 = g_y2 + n * 4096 + (2 * pc) * 64 + (2 * q + oy) * 8;
        ((float4*)d0)[0] = make_float4(c0r[0], c0r[1], c0r[2], c0r[3]);
        ((float4*)d0)[1] = make_float4(c0r[4], c0r[5], c0r[6], c0r[7]);
        float* d1 = d0 + 64;
        ((float4*)d1)[0] = make_float4(c1r[0], c1r[1], c1r[2], c1r[3]);
        ((float4*)d1)[1] = make_float4(c1r[4], c1r[5], c1r[6], c1r[7]);
    }
    #pragma unroll
    for (int off = 1; off < 4; off <<= 1) {    // reduce over the 4 q lanes
        sp = add2(sp, __shfl_xor_sync(0xffffffffu, sp, off));
        qp = add2(qp, __shfl_xor_sync(0xffffffffu, qp, off));
    }
    if (q == 0) {
        float s0, s1, q0, q1;
        unpack2(sp, s0, s1);
        unpack2(qp, q0, q1);
        atomicAdd(&g_sum2[2 * pc],     (double)s0);
        atomicAdd(&g_sum2[2 * pc + 1], (double)s1);
        atomicAdd(&g_sqs2[2 * pc],     (double)q0);
        atomicAdd(&g_sqs2[2 * pc + 1], (double)q1);
    }
}

// ---------------------------------------------------------------------------
// Launch 5: BN + ReLU + maxpool y2 -> h2.
// ---------------------------------------------------------------------------
__global__ __launch_bounds__(256) void k_bnpool2(const float* __restrict__ g, const float* __restrict__ be) {
    __shared__ float sA[64], sB[64];
    if (threadIdx.x < 64) {
        int c = threadIdx.x;
        const double invM = 1.0 / (4096.0 * 64.0);
        double mean = g_sum2[c] * invM;
        double var  = g_sqs2[c] * invM - mean * mean;
        float A = g[c] * rsqrtf((float)var + 1e-5f);
        sA[c] = A;
        sB[c] = be[c] - (float)mean * A;
    }
    __syncthreads();
    int tB = blockIdx.x * 256 + threadIdx.x;
    int base = tB * 4;
    int n = base >> 10;
    int r = base & 1023;
    int c = r >> 4;
    int py = (r & 15) >> 2;
    const float* src = g_y2 + n * 4096 + c * 64 + py * 16;
    float4 a = ((const float4*)src)[0];
    float4 b = ((const float4*)src)[1];
    float4 e = ((const float4*)src)[2];
    float4 d = ((const float4*)src)[3];
    float A = sA[c], B = sB[c];
    float4 o;
    o.x = fmaxf(fmaxf(fmaxf(fmaf(A, a.x, B), fmaf(A, a.y, B)), fmaxf(fmaf(A, e.x, B), fmaf(A, e.y, B))), 0.f);
    o.y = fmaxf(fmaxf(fmaxf(fmaf(A, a.z, B), fmaf(A, a.w, B)), fmaxf(fmaf(A, e.z, B), fmaf(A, e.w, B))), 0.f);
    o.z = fmaxf(fmaxf(fmaxf(fmaf(A, b.x, B), fmaf(A, b.y, B)), fmaxf(fmaf(A, d.x, B), fmaf(A, d.y, B))), 0.f);
    o.w = fmaxf(fmaxf(fmaxf(fmaf(A, b.z, B), fmaf(A, b.w, B)), fmaxf(fmaf(A, d.z, B), fmaf(A, d.w, B))), 0.f);
    *(float4*)(g_h2 + base) = o;
}

// ---------------------------------------------------------------------------
// Launch 6: fc1 GEMM (f32x2 column-paired, scalar A tile) + column stats.
// ---------------------------------------------------------------------------
__global__ __launch_bounds__(256) void k_fc1() {
    __shared__ float As[16][64];
    __shared__ float Bs[16][64];
    __shared__ float scol[64], scol2[64];
    int tid = threadIdx.x;
    if (tid < 64) { scol[tid] = 0.f; scol2[tid] = 0.f; }

    int m0 = blockIdx.y * 64;
    int n0 = blockIdx.x * 64;
    int lr = tid >> 2;
    int lk = (tid & 3) * 4;
    const float* Aload = g_h2   + (m0 + lr) * 1024 + lk;
    const float* Bload = g_wf1q + (n0 + lr) * 1024 + lk;
    int tx = tid & 15, ty = tid >> 4;

    u64 accp[4][2];
    #pragma unroll
    for (int i = 0; i < 4; i++) { accp[i][0] = 0ull; accp[i][1] = 0ull; }

    for (int k0 = 0; k0 < 1024; k0 += 16) {
        float4 av = *(const float4*)(Aload + k0);
        float4 bv = *(const float4*)(Bload + k0);
        __syncthreads();
        As[lk + 0][lr] = av.x; As[lk + 1][lr] = av.y;
        As[lk + 2][lr] = av.z; As[lk + 3][lr] = av.w;
        Bs[lk + 0][lr] = bv.x; Bs[lk + 1][lr] = bv.y;
        Bs[lk + 2][lr] = bv.z; Bs[lk + 3][lr] = bv.w;
        __syncthreads();
        #pragma unroll
        for (int k = 0; k < 16; k++) {
            float4 a = *(const float4*)&As[k][ty * 4];
            float4 b = *(const float4*)&Bs[k][tx * 4];
            u64 b01 = pack2(b.x, b.y), b23 = pack2(b.z, b.w);
            u64 a0 = rep2(a.x), a1 = rep2(a.y), a2 = rep2(a.z), a3 = rep2(a.w);
            ffma2(accp[0][0], a0, b01); ffma2(accp[0][1], a0, b23);
            ffma2(accp[1][0], a1, b01); ffma2(accp[1][1], a1, b23);
            ffma2(accp[2][0], a2, b01); ffma2(accp[2][1], a2, b23);
            ffma2(accp[3][0], a3, b01); ffma2(accp[3][1], a3, b23);
        }
    }
    float acc[4][4];
    #pragma unroll
    for (int i = 0; i < 4; i++) {
        unpack2(accp[i][0], acc[i][0], acc[i][1]);
        unpack2(accp[i][1], acc[i][2], acc[i][3]);
    }
    #pragma unroll
    for (int i = 0; i < 4; i++) {
        int row = m0 + ty * 4 + i;
        *(float4*)(g_y3 + row * 512 + n0 + tx * 4) =
            make_float4(acc[i][0], acc[i][1], acc[i][2], acc[i][3]);
    }
    #pragma unroll
    for (int j = 0; j < 4; j++) {
        float s = 0.f, q = 0.f;
        #pragma unroll
        for (int i = 0; i < 4; i++) { s += acc[i][j]; q = fmaf(acc[i][j], acc[i][j], q); }
        atomicAdd(&scol[tx * 4 + j], s);
        atomicAdd(&scol2[tx * 4 + j], q);
    }
    __syncthreads();
    if (tid < 64) {
        atomicAdd(&g_sum3[n0 + tid], (double)scol[tid]);
        atomicAdd(&g_sqs3[n0 + tid], (double)scol2[tid]);
    }
}

// ---------------------------------------------------------------------------
// Launch 7: fc2 fused with bn1d+relu. Warp per row.
// ---------------------------------------------------------------------------
__global__ __launch_bounds__(256) void k_fc2(float* __restrict__ out, const float* __restrict__ bf2,
                                             const float* __restrict__ g3, const float* __restrict__ be3) {
    __shared__ float sw[5120];
    __shared__ float sA[512], sB[512];
    __shared__ float sb[16];
    for (int i = threadIdx.x; i < 5120; i += 256) sw[i] = g_wf2q[i];
    for (int i = threadIdx.x; i < 512; i += 256) {
        const double invM = 1.0 / 4096.0;
        double mean = g_sum3[i] * invM;
        double var  = g_sqs3[i] * invM - mean * mean;
        float A = g3[i] * rsqrtf((float)var + 1e-5f);
        sA[i] = A;
        sB[i] = be3[i] - (float)mean * A;
    }
    if (threadIdx.x < 10) sb[threadIdx.x] = bf2[threadIdx.x];
    __syncthreads();

    int warp = threadIdx.x >> 5, lane = threadIdx.x & 31;
    int n = blockIdx.x * 8 + warp;
    const float* yr = g_y3 + n * 512;
    float acc[10];
    #pragma unroll
    for (int o = 0; o < 10; o++) acc[o] = 0.f;
    for (int f = lane; f < 512; f += 32) {
        float a = fmaxf(fmaf(sA[f], yr[f], sB[f]), 0.f);
        #pragma unroll
        for (int o = 0; o < 10; o++) acc[o] = fmaf(a, sw[o * 512 + f], acc[o]);
    }
    #pragma unroll
    for (int o = 0; o < 10; o++) {
        float s = acc[o];
        #pragma unroll
        for (int off = 16; off; off >>= 1) s += __shfl_xor_sync(0xffffffffu, s, off);
        if (lane == 0) out[n * 10 + o] = s + sb[o];
    }
}

// ---------------------------------------------------------------------------
extern "C" void kernel_launch(void* const* d_in, const int* in_sizes, int n_in,
                              void* d_out, int out_size) {
    const float* x   = (const float*)d_in[0];
    const float* w1  = (const float*)d_in[1];
    const float* g1  = (const float*)d_in[3];
    const float* be1 = (const float*)d_in[4];
    const float* w2  = (const float*)d_in[5];
    const float* g2  = (const float*)d_in[7];
    const float* be2 = (const float*)d_in[8];
    const float* wf1 = (const float*)d_in[9];
    const float* g3  = (const float*)d_in[11];
    const float* be3 = (const float*)d_in[12];
    const float* wf2 = (const float*)d_in[13];
    const float* bf2 = (const float*)d_in[14];
    float* out = (float*)d_out;

    k_absmax<<<96, 256>>>(w1, w2, wf1, wf2);        // 1
    k_conv1<<<4096, 384>>>(x, w1, w2, wf1, wf2);    // 2
    k_bnpool1<<<73728, 256>>>(g1, be1);             // 3
    k_conv2<<<2048, 256>>>();                       // 4  <- profiled (2 img/CTA)
    k_bnpool2<<<4096, 256>>>(g2, be2);              // 5
    dim3 g_fc1(8, 64);
    k_fc1<<<g_fc1, 256>>>();                        // 6
    k_fc2<<<512, 256>>>(out, bf2, g3, be3);         // 7
}

// round 6
// speedup vs baseline: 3.4694x; 1.1872x over previous
#include <cuda_runtime.h>

// ---------------------------------------------------------------------------
// MNIST TWN CNN forward, batch 4096, fp32.
// R6: producers emit per-pool-window max/min (exact); consumers apply
//     BN affine + relu + sign-select on load. bnpool1 eliminated.
// Launches: absmax, conv1, fin1, conv2(#4, profiled), bnpool2, fc1, fc2.
// ---------------------------------------------------------------------------

#define NIMG 4096
typedef unsigned long long u64;

__device__ __forceinline__ u64 pack2(float lo, float hi) {
    u64 r; asm("mov.b64 %0,{%1,%2};" : "=l"(r) : "f"(lo), "f"(hi)); return r;
}
__device__ __forceinline__ u64 rep2(float v) { return pack2(v, v); }
__device__ __forceinline__ void unpack2(u64 p, float& lo, float& hi) {
    asm("mov.b64 {%0,%1},%2;" : "=f"(lo), "=f"(hi) : "l"(p));
}
__device__ __forceinline__ void ffma2(u64& d, u64 a, u64 b) {
    asm("fma.rn.f32x2 %0,%1,%2,%0;" : "+l"(d) : "l"(a), "l"(b));
}
__device__ __forceinline__ u64 add2(u64 a, u64 b) {
    u64 r; asm("add.rn.f32x2 %0,%1,%2;" : "=l"(r) : "l"(a), "l"(b)); return r;
}
__device__ __forceinline__ float ternary(float w, float t) {
    return (w > t ? 1.0f : 0.0f) - (w < -t ? 1.0f : 0.0f);
}
__device__ __forceinline__ float bnsel(float A, float B, float mx, float mn) {
    return fmaxf(A > 0.f ? fmaf(A, mx, B) : fmaf(A, mn, B), 0.f);
}

// ---- device scratch (static only) -----------------------------------------
static __device__ u64   g_w2p[32 * 800];         // [ci][pc][25] channel-pair packed
static __device__ float g_wf1q[512 * 1024];
static __device__ float g_wf2q[10 * 512];
static __device__ float g_pmax[96][4];

static __device__ double g_sum1[32],  g_sqs1[32];
static __device__ double g_sum2[64],  g_sqs2[64];
static __device__ double g_sum3[512], g_sqs3[512];

static __device__ float g_sc1[32], g_sh1[32];    // layer1 BN affine (fin1)

static __device__ float g_m1max[NIMG * 32 * 144];  // conv1 pooled window max
static __device__ float g_m1min[NIMG * 32 * 144];  // conv1 pooled window min
static __device__ float g_m2max[NIMG * 1024];      // conv2 pooled window max
static __device__ float g_m2min[NIMG * 1024];      // conv2 pooled window min
static __device__ float g_h2[NIMG * 1024];         // pooled/flat layer2 activations
static __device__ float g_y3[NIMG * 512];          // fc1 raw

// ---------------------------------------------------------------------------
// Launch 1: abs-max partials (grid MUST be 96). Block 0 zeros stat accums.
// ---------------------------------------------------------------------------
__global__ __launch_bounds__(256) void k_absmax(const float* __restrict__ w1, const float* __restrict__ w2,
                                                const float* __restrict__ wf1, const float* __restrict__ wf2) {
    __shared__ float sm[8][4];
    int tid = threadIdx.x;
    if (blockIdx.x == 0) {
        if (tid < 32) { g_sum1[tid] = 0.0; g_sqs1[tid] = 0.0; }
        if (tid < 64) { g_sum2[tid] = 0.0; g_sqs2[tid] = 0.0; }
        g_sum3[tid] = 0.0;       g_sqs3[tid] = 0.0;
        g_sum3[tid + 256] = 0.0; g_sqs3[tid + 256] = 0.0;
    }
    int gid = blockIdx.x * 256 + tid;
    int stride = 96 * 256;
    float m0 = 0.f, m1 = 0.f, m2 = 0.f, m3 = 0.f;
    for (int i = gid; i < 800;    i += stride) m0 = fmaxf(m0, fabsf(w1[i]));
    for (int i = gid; i < 51200;  i += stride) m1 = fmaxf(m1, fabsf(w2[i]));
    for (int i = gid; i < 524288; i += stride) m2 = fmaxf(m2, fabsf(wf1[i]));
    for (int i = gid; i < 5120;   i += stride) m3 = fmaxf(m3, fabsf(wf2[i]));
    #pragma unroll
    for (int off = 16; off; off >>= 1) {
        m0 = fmaxf(m0, __shfl_xor_sync(0xffffffffu, m0, off));
        m1 = fmaxf(m1, __shfl_xor_sync(0xffffffffu, m1, off));
        m2 = fmaxf(m2, __shfl_xor_sync(0xffffffffu, m2, off));
        m3 = fmaxf(m3, __shfl_xor_sync(0xffffffffu, m3, off));
    }
    int w = tid >> 5;
    if ((tid & 31) == 0) { sm[w][0] = m0; sm[w][1] = m1; sm[w][2] = m2; sm[w][3] = m3; }
    __syncthreads();
    if (tid == 0) {
        float r0 = 0.f, r1 = 0.f, r2 = 0.f, r3 = 0.f;
        #pragma unroll
        for (int i = 0; i < 8; i++) {
            r0 = fmaxf(r0, sm[i][0]); r1 = fmaxf(r1, sm[i][1]);
            r2 = fmaxf(r2, sm[i][2]); r3 = fmaxf(r3, sm[i][3]);
        }
        g_pmax[blockIdx.x][0] = r0; g_pmax[blockIdx.x][1] = r1;
        g_pmax[blockIdx.x][2] = r2; g_pmax[blockIdx.x][3] = r3;
    }
}

// ---------------------------------------------------------------------------
// Launch 2: conv1 + stats + pooled max/min. One block per image, 192 threads
// = 16 channel-pairs x 12 pooled rows. Thread computes output rows 2q,2q+1
// (sliding weight-row window), pools 2x2 in registers, writes max & min.
// Side job: distributed weight quantization.
// ---------------------------------------------------------------------------
__global__ __launch_bounds__(192) void k_conv1(const float* __restrict__ x,  const float* __restrict__ w1,
                                               const float* __restrict__ w2, const float* __restrict__ wf1,
                                               const float* __restrict__ wf2) {
    __shared__ u64 sx[784];
    __shared__ u64 sw1[400];
    __shared__ float sthr[4];
    __shared__ float ssum[32], ssq[32];
    int tid = threadIdx.x, n = blockIdx.x;

    if (tid < 4) {
        float m = 0.f;
        #pragma unroll 8
        for (int i = 0; i < 96; i++) m = fmaxf(m, g_pmax[i][tid]);
        sthr[tid] = 0.05f * m;
    }
    if (tid < 32) { ssum[tid] = 0.f; ssq[tid] = 0.f; }
    __syncthreads();

    for (int i = tid; i < 400; i += 192) {
        int cp = i / 25, k = i - cp * 25;
        float t0 = sthr[0];
        sw1[i] = pack2(ternary(w1[(2 * cp) * 25 + k], t0),
                       ternary(w1[(2 * cp + 1) * 25 + k], t0));
    }
    for (int i = tid; i < 784; i += 192) sx[i] = rep2(x[n * 784 + i]);

    {   // distributed quantization: gu in [0, 4096*192) covers 549888 units
        int gu = n * 192 + tid;
        if (gu < 25600) {
            int ci = gu / 800, r = gu - ci * 800;
            int pc = r / 25, k = r - pc * 25;
            float t1 = sthr[1];
            ((float2*)g_w2p)[gu] = make_float2(ternary(w2[(2 * pc) * 800 + ci * 25 + k], t1),
                                               ternary(w2[(2 * pc + 1) * 800 + ci * 25 + k], t1));
        } else if (gu < 25600 + 524288) {
            g_wf1q[gu - 25600] = ternary(wf1[gu - 25600], sthr[2]);
        } else if (gu < 25600 + 524288 + 5120) {
            g_wf2q[gu - 549888] = ternary(wf2[gu - 549888], sthr[3]);
        }
    }
    __syncthreads();

    int cp = tid / 12;                 // channel pair (2cp, 2cp+1)
    int q  = tid - cp * 12;            // pooled row: output rows 2q, 2q+1
    const u64* wbase = sw1 + cp * 25;
    u64 sp = 0ull, qp = 0ull;
    float* pmx0 = g_m1max + n * 4608 + (2 * cp) * 144 + q * 12;
    float* pmn0 = g_m1min + n * 4608 + (2 * cp) * 144 + q * 12;

    #pragma unroll
    for (int ob = 0; ob < 24; ob += 4) {
        u64 a0[4] = {0ull, 0ull, 0ull, 0ull};
        u64 a1[4] = {0ull, 0ull, 0ull, 0ull};
        u64 pw0, pw1, pw2, pw3, pw4;
        pw0 = pw1 = pw2 = pw3 = pw4 = 0ull;
        #pragma unroll
        for (int rr = 0; rr < 6; rr++) {
            const ulonglong2* xr = (const ulonglong2*)(sx + (2 * q + rr) * 28 + ob);
            ulonglong2 v0 = xr[0], v1 = xr[1], v2 = xr[2], v3 = xr[3];
            u64 X[8] = { v0.x, v0.y, v1.x, v1.y, v2.x, v2.y, v3.x, v3.y };
            if (rr >= 1) {
                #pragma unroll
                for (int o = 0; o < 4; o++) {
                    ffma2(a1[o], X[o],     pw0);
                    ffma2(a1[o], X[o + 1], pw1);
                    ffma2(a1[o], X[o + 2], pw2);
                    ffma2(a1[o], X[o + 3], pw3);
                    ffma2(a1[o], X[o + 4], pw4);
                }
            }
            if (rr < 5) {
                const u64* wr = wbase + rr * 5;
                u64 c0 = wr[0], c1 = wr[1], c2 = wr[2], c3 = wr[3], c4 = wr[4];
                #pragma unroll
                for (int o = 0; o < 4; o++) {
                    ffma2(a0[o], X[o],     c0);
                    ffma2(a0[o], X[o + 1], c1);
                    ffma2(a0[o], X[o + 2], c2);
                    ffma2(a0[o], X[o + 3], c3);
                    ffma2(a0[o], X[o + 4], c4);
                }
                pw0 = c0; pw1 = c1; pw2 = c2; pw3 = c3; pw4 = c4;
            }
        }
        // stats over all 8 raw outputs (both rows)
        float r0c0[4], r0c1[4], r1c0[4], r1c1[4];
        #pragma unroll
        for (int o = 0; o < 4; o++) {
            sp = add2(sp, a0[o]); ffma2(qp, a0[o], a0[o]);
            sp = add2(sp, a1[o]); ffma2(qp, a1[o], a1[o]);
            unpack2(a0[o], r0c0[o], r0c1[o]);
            unpack2(a1[o], r1c0[o], r1c1[o]);
        }
        // 2x2 pooling: two pooled columns per block
        float mx0[2], mn0[2], mx1[2], mn1[2];
        #pragma unroll
        for (int j = 0; j < 2; j++) {
            float A0 = r0c0[2 * j], B0 = r0c0[2 * j + 1], C0 = r1c0[2 * j], D0 = r1c0[2 * j + 1];
            mx0[j] = fmaxf(fmaxf(A0, B0), fmaxf(C0, D0));
            mn0[j] = fminf(fminf(A0, B0), fminf(C0, D0));
            float A1 = r0c1[2 * j], B1 = r0c1[2 * j + 1], C1 = r1c1[2 * j], D1 = r1c1[2 * j + 1];
            mx1[j] = fmaxf(fmaxf(A1, B1), fmaxf(C1, D1));
            mn1[j] = fminf(fminf(A1, B1), fminf(C1, D1));
        }
        int pc2 = ob >> 1;
        *(float2*)(pmx0 + pc2)       = make_float2(mx0[0], mx0[1]);
        *(float2*)(pmn0 + pc2)       = make_float2(mn0[0], mn0[1]);
        *(float2*)(pmx0 + 144 + pc2) = make_float2(mx1[0], mx1[1]);
        *(float2*)(pmn0 + 144 + pc2) = make_float2(mn1[0], mn1[1]);
    }
    float s0, s1, q0, q1;
    unpack2(sp, s0, s1);
    unpack2(qp, q0, q1);
    atomicAdd(&ssum[2 * cp],     s0);
    atomicAdd(&ssum[2 * cp + 1], s1);
    atomicAdd(&ssq[2 * cp],      q0);
    atomicAdd(&ssq[2 * cp + 1],  q1);
    __syncthreads();
    if (tid < 32) {
        atomicAdd(&g_sum1[tid], (double)ssum[tid]);
        atomicAdd(&g_sqs1[tid], (double)ssq[tid]);
    }
}

// ---------------------------------------------------------------------------
// Launch 3: finalize layer-1 BN affine.
// ---------------------------------------------------------------------------
__global__ void k_fin1(const float* __restrict__ g, const float* __restrict__ be) {
    int i = threadIdx.x;
    if (i >= 32) return;
    const double invM = 1.0 / (4096.0 * 576.0);
    double mean = g_sum1[i] * invM;
    double var  = g_sqs1[i] * invM - mean * mean;
    float A = g[i] * rsqrtf((float)var + 1e-5f);
    g_sc1[i] = A;
    g_sh1[i] = be[i] - (float)mean * A;
}

// ---------------------------------------------------------------------------
// Launch 4 (PROFILED): conv2. Input = relu(affine-select(max,min)) applied
// during SMEM staging. 2 images/CTA, 256 thr = 2img x 32pc x 4 rowpairs.
// Writes pooled max/min of raw y2 + per-channel stats.
// ---------------------------------------------------------------------------
__global__ __launch_bounds__(256) void k_conv2() {
    __shared__ float sin_[2][4608];            // 36.9 KB scalar input
    __shared__ u64 swt[2][800];                // 12.8 KB weight double buffer
    __shared__ float sA1[32], sB1[32];
    int tid = threadIdx.x;
    int n0 = blockIdx.x * 2;

    if (tid < 32) { sA1[tid] = g_sc1[tid]; sB1[tid] = g_sh1[tid]; }
    __syncthreads();

    {   // staged load with fused bn+relu+pool-select (float4 granularity)
        const float4* mx4 = (const float4*)(g_m1max + n0 * 4608);
        const float4* mn4 = (const float4*)(g_m1min + n0 * 4608);
        float4* s4 = (float4*)sin_;
        for (int i = tid; i < 2304; i += 256) {
            int c = (i % 1152) / 36;
            float A = sA1[c], B = sB1[c];
            float4 mx = mx4[i], mn = mn4[i];
            float4 v;
            v.x = bnsel(A, B, mx.x, mn.x);
            v.y = bnsel(A, B, mx.y, mn.y);
            v.z = bnsel(A, B, mx.z, mn.z);
            v.w = bnsel(A, B, mx.w, mn.w);
            s4[i] = v;
        }
    }
    for (int j = tid; j < 800; j += 256) swt[0][j] = g_w2p[j];
    __syncthreads();

    int img = tid >> 7;
    int t   = tid & 127;
    int pc  = t >> 2;                          // channel pair (2pc, 2pc+1)
    int q   = t & 3;                           // output rows 2q, 2q+1
    const float* ib = sin_[img] + q * 24;

    u64 acc[2][8];
    #pragma unroll
    for (int oy = 0; oy < 2; oy++)
        #pragma unroll
        for (int px = 0; px < 8; px++) acc[oy][px] = 0ull;

    for (int ci = 0; ci < 32; ci++) {
        if (ci < 31) {
            const u64* ws = g_w2p + (ci + 1) * 800;
            for (int j = tid; j < 800; j += 256) swt[(ci + 1) & 1][j] = ws[j];
        }
        const u64* wp = swt[ci & 1] + pc * 25;
        const float* rb = ib + ci * 144;
        u64 pw0, pw1, pw2, pw3, pw4;
        pw0 = pw1 = pw2 = pw3 = pw4 = 0ull;
        #pragma unroll
        for (int rr = 0; rr < 6; rr++) {
            float4 f0 = *(const float4*)(rb + rr * 12);
            float4 f1 = *(const float4*)(rb + rr * 12 + 4);
            float4 f2 = *(const float4*)(rb + rr * 12 + 8);
            u64 R[12] = { rep2(f0.x), rep2(f0.y), rep2(f0.z), rep2(f0.w),
                          rep2(f1.x), rep2(f1.y), rep2(f1.z), rep2(f1.w),
                          rep2(f2.x), rep2(f2.y), rep2(f2.z), rep2(f2.w) };
            if (rr >= 1) {
                #pragma unroll
                for (int px = 0; px < 8; px++) {
                    ffma2(acc[1][px], R[px],     pw0);
                    ffma2(acc[1][px], R[px + 1], pw1);
                    ffma2(acc[1][px], R[px + 2], pw2);
                    ffma2(acc[1][px], R[px + 3], pw3);
                    ffma2(acc[1][px], R[px + 4], pw4);
                }
            }
            if (rr < 5) {
                const u64* wr = wp + rr * 5;
                u64 c0 = wr[0], c1 = wr[1], c2 = wr[2], c3 = wr[3], c4 = wr[4];
                #pragma unroll
                for (int px = 0; px < 8; px++) {
                    ffma2(acc[0][px], R[px],     c0);
                    ffma2(acc[0][px], R[px + 1], c1);
                    ffma2(acc[0][px], R[px + 2], c2);
                    ffma2(acc[0][px], R[px + 3], c3);
                    ffma2(acc[0][px], R[px + 4], c4);
                }
                pw0 = c0; pw1 = c1; pw2 = c2; pw3 = c3; pw4 = c4;
            }
        }
        __syncthreads();
    }

    int n = n0 + img;
    u64 sp = 0ull, qp = 0ull;
    float r0c0[8], r0c1[8], r1c0[8], r1c1[8];
    #pragma unroll
    for (int px = 0; px < 8; px++) {
        sp = add2(sp, acc[0][px]); ffma2(qp, acc[0][px], acc[0][px]);
        sp = add2(sp, acc[1][px]); ffma2(qp, acc[1][px], acc[1][px]);
        unpack2(acc[0][px], r0c0[px], r0c1[px]);
        unpack2(acc[1][px], r1c0[px], r1c1[px]);
    }
    float pm0[4], pn0[4], pm1[4], pn1[4];
    #pragma unroll
    for (int j = 0; j < 4; j++) {
        pm0[j] = fmaxf(fmaxf(r0c0[2 * j], r0c0[2 * j + 1]), fmaxf(r1c0[2 * j], r1c0[2 * j + 1]));
        pn0[j] = fminf(fminf(r0c0[2 * j], r0c0[2 * j + 1]), fminf(r1c0[2 * j], r1c0[2 * j + 1]));
        pm1[j] = fmaxf(fmaxf(r0c1[2 * j], r0c1[2 * j + 1]), fmaxf(r1c1[2 * j], r1c1[2 * j + 1]));
        pn1[j] = fminf(fminf(r0c1[2 * j], r0c1[2 * j + 1]), fminf(r1c1[2 * j], r1c1[2 * j + 1]));
    }
    int ob = n * 1024 + (2 * pc) * 16 + q * 4;
    *(float4*)(g_m2max + ob)      = make_float4(pm0[0], pm0[1], pm0[2], pm0[3]);
    *(float4*)(g_m2min + ob)      = make_float4(pn0[0], pn0[1], pn0[2], pn0[3]);
    *(float4*)(g_m2max + ob + 16) = make_float4(pm1[0], pm1[1], pm1[2], pm1[3]);
    *(float4*)(g_m2min + ob + 16) = make_float4(pn1[0], pn1[1], pn1[2], pn1[3]);

    #pragma unroll
    for (int off = 1; off < 4; off <<= 1) {
        sp = add2(sp, __shfl_xor_sync(0xffffffffu, sp, off));
        qp = add2(qp, __shfl_xor_sync(0xffffffffu, qp, off));
    }
    if (q == 0) {
        float s0, s1, q0, q1;
        unpack2(sp, s0, s1);
        unpack2(qp, q0, q1);
        atomicAdd(&g_sum2[2 * pc],     (double)s0);
        atomicAdd(&g_sum2[2 * pc + 1], (double)s1);
        atomicAdd(&g_sqs2[2 * pc],     (double)q0);
        atomicAdd(&g_sqs2[2 * pc + 1], (double)q1);
    }
}

// ---------------------------------------------------------------------------
// Launch 5: BN affine + relu + select on pooled extrema -> h2.
// ---------------------------------------------------------------------------
__global__ __launch_bounds__(256) void k_bnpool2(const float* __restrict__ g, const float* __restrict__ be) {
    __shared__ float sA[64], sB[64];
    if (threadIdx.x < 64) {
        int c = threadIdx.x;
        const double invM = 1.0 / (4096.0 * 64.0);
        double mean = g_sum2[c] * invM;
        double var  = g_sqs2[c] * invM - mean * mean;
        float A = g[c] * rsqrtf((float)var + 1e-5f);
        sA[c] = A;
        sB[c] = be[c] - (float)mean * A;
    }
    __syncthreads();
    int tB = blockIdx.x * 256 + threadIdx.x;   // < 1048576
    int base = tB * 4;
    int c = (base & 1023) >> 4;
    float4 mx = *(const float4*)(g_m2max + base);
    float4 mn = *(const float4*)(g_m2min + base);
    float A = sA[c], B = sB[c];
    float4 o;
    o.x = bnsel(A, B, mx.x, mn.x);
    o.y = bnsel(A, B, mx.y, mn.y);
    o.z = bnsel(A, B, mx.z, mn.z);
    o.w = bnsel(A, B, mx.w, mn.w);
    *(float4*)(g_h2 + base) = o;
}

// ---------------------------------------------------------------------------
// Launch 6: fc1 GEMM (f32x2 column-paired, scalar A tile) + column stats.
// ---------------------------------------------------------------------------
__global__ __launch_bounds__(256) void k_fc1() {
    __shared__ float As[16][64];
    __shared__ float Bs[16][64];
    __shared__ float scol[64], scol2[64];
    int tid = threadIdx.x;
    if (tid < 64) { scol[tid] = 0.f; scol2[tid] = 0.f; }

    int m0 = blockIdx.y * 64;
    int n0 = blockIdx.x * 64;
    int lr = tid >> 2;
    int lk = (tid & 3) * 4;
    const float* Aload = g_h2   + (m0 + lr) * 1024 + lk;
    const float* Bload = g_wf1q + (n0 + lr) * 1024 + lk;
    int tx = tid & 15, ty = tid >> 4;

    u64 accp[4][2];
    #pragma unroll
    for (int i = 0; i < 4; i++) { accp[i][0] = 0ull; accp[i][1] = 0ull; }

    for (int k0 = 0; k0 < 1024; k0 += 16) {
        float4 av = *(const float4*)(Aload + k0);
        float4 bv = *(const float4*)(Bload + k0);
        __syncthreads();
        As[lk + 0][lr] = av.x; As[lk + 1][lr] = av.y;
        As[lk + 2][lr] = av.z; As[lk + 3][lr] = av.w;
        Bs[lk + 0][lr] = bv.x; Bs[lk + 1][lr] = bv.y;
        Bs[lk + 2][lr] = bv.z; Bs[lk + 3][lr] = bv.w;
        __syncthreads();
        #pragma unroll
        for (int k = 0; k < 16; k++) {
            float4 a = *(const float4*)&As[k][ty * 4];
            float4 b = *(const float4*)&Bs[k][tx * 4];
            u64 b01 = pack2(b.x, b.y), b23 = pack2(b.z, b.w);
            u64 a0 = rep2(a.x), a1 = rep2(a.y), a2 = rep2(a.z), a3 = rep2(a.w);
            ffma2(accp[0][0], a0, b01); ffma2(accp[0][1], a0, b23);
            ffma2(accp[1][0], a1, b01); ffma2(accp[1][1], a1, b23);
            ffma2(accp[2][0], a2, b01); ffma2(accp[2][1], a2, b23);
            ffma2(accp[3][0], a3, b01); ffma2(accp[3][1], a3, b23);
        }
    }
    float acc[4][4];
    #pragma unroll
    for (int i = 0; i < 4; i++) {
        unpack2(accp[i][0], acc[i][0], acc[i][1]);
        unpack2(accp[i][1], acc[i][2], acc[i][3]);
    }
    #pragma unroll
    for (int i = 0; i < 4; i++) {
        int row = m0 + ty * 4 + i;
        *(float4*)(g_y3 + row * 512 + n0 + tx * 4) =
            make_float4(acc[i][0], acc[i][1], acc[i][2], acc[i][3]);
    }
    #pragma unroll
    for (int j = 0; j < 4; j++) {
        float s = 0.f, q = 0.f;
        #pragma unroll
        for (int i = 0; i < 4; i++) { s += acc[i][j]; q = fmaf(acc[i][j], acc[i][j], q); }
        atomicAdd(&scol[tx * 4 + j], s);
        atomicAdd(&scol2[tx * 4 + j], q);
    }
    __syncthreads();
    if (tid < 64) {
        atomicAdd(&g_sum3[n0 + tid], (double)scol[tid]);
        atomicAdd(&g_sqs3[n0 + tid], (double)scol2[tid]);
    }
}

// ---------------------------------------------------------------------------
// Launch 7: fc2 fused with bn1d+relu. Warp per row.
// ---------------------------------------------------------------------------
__global__ __launch_bounds__(256) void k_fc2(float* __restrict__ out, const float* __restrict__ bf2,
                                             const float* __restrict__ g3, const float* __restrict__ be3) {
    __shared__ float sw[5120];
    __shared__ float sA[512], sB[512];
    __shared__ float sb[16];
    for (int i = threadIdx.x; i < 5120; i += 256) sw[i] = g_wf2q[i];
    for (int i = threadIdx.x; i < 512; i += 256) {
        const double invM = 1.0 / 4096.0;
        double mean = g_sum3[i] * invM;
        double var  = g_sqs3[i] * invM - mean * mean;
        float A = g3[i] * rsqrtf((float)var + 1e-5f);
        sA[i] = A;
        sB[i] = be3[i] - (float)mean * A;
    }
    if (threadIdx.x < 10) sb[threadIdx.x] = bf2[threadIdx.x];
    __syncthreads();

    int warp = threadIdx.x >> 5, lane = threadIdx.x & 31;
    int n = blockIdx.x * 8 + warp;
    const float* yr = g_y3 + n * 512;
    float acc[10];
    #pragma unroll
    for (int o = 0; o < 10; o++) acc[o] = 0.f;
    for (int f = lane; f < 512; f += 32) {
        float a = fmaxf(fmaf(sA[f], yr[f], sB[f]), 0.f);
        #pragma unroll
        for (int o = 0; o < 10; o++) acc[o] = fmaf(a, sw[o * 512 + f], acc[o]);
    }
    #pragma unroll
    for (int o = 0; o < 10; o++) {
        float s = acc[o];
        #pragma unroll
        for (int off = 16; off; off >>= 1) s += __shfl_xor_sync(0xffffffffu, s, off);
        if (lane == 0) out[n * 10 + o] = s + sb[o];
    }
}

// ---------------------------------------------------------------------------
extern "C" void kernel_launch(void* const* d_in, const int* in_sizes, int n_in,
                              void* d_out, int out_size) {
    const float* x   = (const float*)d_in[0];
    const float* w1  = (const float*)d_in[1];
    const float* g1  = (const float*)d_in[3];
    const float* be1 = (const float*)d_in[4];
    const float* w2  = (const float*)d_in[5];
    const float* g2  = (const float*)d_in[7];
    const float* be2 = (const float*)d_in[8];
    const float* wf1 = (const float*)d_in[9];
    const float* g3  = (const float*)d_in[11];
    const float* be3 = (const float*)d_in[12];
    const float* wf2 = (const float*)d_in[13];
    const float* bf2 = (const float*)d_in[14];
    float* out = (float*)d_out;

    k_absmax<<<96, 256>>>(w1, w2, wf1, wf2);        // 1
    k_conv1<<<4096, 192>>>(x, w1, w2, wf1, wf2);    // 2
    k_fin1<<<1, 32>>>(g1, be1);                     // 3
    k_conv2<<<2048, 256>>>();                       // 4  <- profiled
    k_bnpool2<<<4096, 256>>>(g2, be2);              // 5
    dim3 g_fc1(8, 64);
    k_fc1<<<g_fc1, 256>>>();                        // 6
    k_fc2<<<512, 256>>>(out, bf2, g3, be3);         // 7
}